// round 9
// baseline (speedup 1.0000x reference)
#include <cuda_runtime.h>
#include <cuda_fp16.h>
#include <math.h>

#define BATCH   4
#define TQ      2048
#define TK      2048
#define DMODEL  1024
#define NHEADS  16
#define HDIM    64
#define MROWS   (BATCH * TQ)   // 8192

// ---------------- scratch (__device__ globals; no allocation allowed) -------
// "interleaved" = within each 16-element k-block, pair j at slot (j<4?2j:2j-7)
// so every mma.sync fp16 fragment is a single LDS.64.
__device__ __half h_Q[MROWS * DMODEL];   // (b,h,t,hd-interleaved), prescaled 1/8
__device__ __half h_K[MROWS * DMODEL];   // (b,h,t,hd-interleaved)
__device__ __half h_V[MROWS * DMODEL];   // (b,h,hd,t-interleaved)  (V^T)
__device__ __half h_O[MROWS * DMODEL];   // (b,t,dmodel-interleaved)
__device__ __half h_Xq[MROWS * DMODEL];  // x_q  interleaved
__device__ __half h_Xkv[MROWS * DMODEL]; // x_kv interleaved
__device__ __half h_Wq[DMODEL * DMODEL];
__device__ __half h_Wk[DMODEL * DMODEL];
__device__ __half h_Wv[DMODEL * DMODEL];
__device__ __half h_Wo[DMODEL * DMODEL];
__device__ __half h_Mask[TQ * TK];       // additive mask, fp16

// ---------------- helpers ----------------------------------------------------
__device__ __forceinline__ void mma_f16(float* d, const unsigned* a, const unsigned* b) {
    asm volatile(
        "mma.sync.aligned.m16n8k16.row.col.f32.f16.f16.f32 "
        "{%0,%1,%2,%3}, {%4,%5,%6,%7}, {%8,%9}, {%0,%1,%2,%3};"
        : "+f"(d[0]), "+f"(d[1]), "+f"(d[2]), "+f"(d[3])
        : "r"(a[0]), "r"(a[1]), "r"(a[2]), "r"(a[3]), "r"(b[0]), "r"(b[1]));
}

__device__ __forceinline__ unsigned pack_h2(float lo, float hi) {
    __half2 h = __floats2half2_rn(lo, hi);
    return *(unsigned*)&h;
}

__device__ __forceinline__ void cp16(void* smem_dst, const void* gmem_src) {
    unsigned s = (unsigned)__cvta_generic_to_shared(smem_dst);
    asm volatile("cp.async.cg.shared.global [%0], [%1], 16;" :: "r"(s), "l"(gmem_src));
}

__device__ __forceinline__ int islot(int j) { return (j < 4) ? 2 * j : 2 * j - 7; }

// ---------------- pre-convert: fp32 -> fp16, k-pair-interleaved ---------------
__global__ void cvt_h16_kernel(const float* __restrict__ src, __half* __restrict__ dst,
                               int n, float scale)
{
    int i8 = (blockIdx.x * blockDim.x + threadIdx.x) * 8;
    if (i8 >= n) return;
    float4 v0 = *(const float4*)&src[i8];
    float4 v1 = *(const float4*)&src[i8 + 4];
    int base2 = (i8 & ~15) >> 1;
    int hi = (i8 & 15) ? 1 : 0;
    __half2* d = (__half2*)dst;
    d[base2 + 0 + hi] = __floats2half2_rn(v0.x * scale, v0.y * scale);
    d[base2 + 2 + hi] = __floats2half2_rn(v0.z * scale, v0.w * scale);
    d[base2 + 4 + hi] = __floats2half2_rn(v1.x * scale, v1.y * scale);
    d[base2 + 6 + hi] = __floats2half2_rn(v1.z * scale, v1.w * scale);
}

// plain fp32 -> fp16 (for the additive mask)
__global__ void cvt_mask_kernel(const float* __restrict__ src, __half* __restrict__ dst, int n) {
    int i8 = (blockIdx.x * blockDim.x + threadIdx.x) * 8;
    if (i8 >= n) return;
    float4 v0 = *(const float4*)&src[i8];
    float4 v1 = *(const float4*)&src[i8 + 4];
    __half2 h[4];
    h[0] = __floats2half2_rn(v0.x, v0.y);
    h[1] = __floats2half2_rn(v0.z, v0.w);
    h[2] = __floats2half2_rn(v1.x, v1.y);
    h[3] = __floats2half2_rn(v1.z, v1.w);
    *(uint4*)&dst[i8] = *(uint4*)h;
}

// ---------------- fp16 GEMM: C = A(M,K) @ W(N,K)^T ----------------------------
// 128x128x64 block, 256 threads, 8 warps of 64x32, cp.async double buffer.
#define BM   128
#define BN   128
#define BKH  64
#define GST  80     // halves; 40 words = 8 mod 32 -> conflict-free LDS.64

template <int MODE>
__global__ void __launch_bounds__(256, 2)
gemm_h16(const __half* __restrict__ A, const __half* __restrict__ W,
         void* __restrict__ Cv, float scale)
{
    extern __shared__ __half smh[];
    __half* As = smh;                      // [2][BM][GST]
    __half* Ws = smh + 2 * BM * GST;       // [2][BN][GST]

    const int tid  = threadIdx.x;
    const int lane = tid & 31;
    const int warp = tid >> 5;
    const int wm   = warp >> 2;
    const int wn   = warp & 3;
    const int bm   = blockIdx.y * BM;
    const int bn   = blockIdx.x * BN;
    const int lr   = lane >> 2;
    const int lc   = lane & 3;

    float acc[4][4][4];
#pragma unroll
    for (int i = 0; i < 4; i++)
#pragma unroll
        for (int j = 0; j < 4; j++)
#pragma unroll
            for (int c = 0; c < 4; c++) acc[i][j][c] = 0.f;

    const int NIT = DMODEL / BKH;  // 16

    auto load_stage = [&](int st, int k0) {
#pragma unroll
        for (int r = 0; r < 4; r++) {
            int id  = tid + r * 256;
            int m   = id >> 3;
            int c8  = (id & 7) * 8;
            cp16(&As[(st * BM + m) * GST + c8], &A[(size_t)(bm + m) * DMODEL + k0 + c8]);
        }
#pragma unroll
        for (int r = 0; r < 4; r++) {
            int id  = tid + r * 256;
            int m   = id >> 3;
            int c8  = (id & 7) * 8;
            cp16(&Ws[(st * BN + m) * GST + c8], &W[(size_t)(bn + m) * DMODEL + k0 + c8]);
        }
        asm volatile("cp.async.commit_group;");
    };

    load_stage(0, 0);

    for (int it = 0; it < NIT; it++) {
        if (it + 1 < NIT) {
            load_stage((it + 1) & 1, (it + 1) * BKH);
            asm volatile("cp.async.wait_group 1;");
        } else {
            asm volatile("cp.async.wait_group 0;");
        }
        __syncthreads();
        const __half* Ab = &As[(it & 1) * BM * GST];
        const __half* Wb = &Ws[(it & 1) * BN * GST];

#pragma unroll
        for (int kk = 0; kk < 4; kk++) {
            unsigned af[4][4], bf[4][2];
#pragma unroll
            for (int mf = 0; mf < 4; mf++) {
                const int row = wm * 64 + mf * 16 + lr;
                uint2 u0 = *(const uint2*)&Ab[row * GST + kk * 16 + 4 * lc];
                uint2 u1 = *(const uint2*)&Ab[(row + 8) * GST + kk * 16 + 4 * lc];
                af[mf][0] = u0.x; af[mf][1] = u1.x; af[mf][2] = u0.y; af[mf][3] = u1.y;
            }
#pragma unroll
            for (int nf = 0; nf < 4; nf++) {
                const int row = wn * 32 + nf * 8 + lr;
                uint2 u = *(const uint2*)&Wb[row * GST + kk * 16 + 4 * lc];
                bf[nf][0] = u.x; bf[nf][1] = u.y;
            }
#pragma unroll
            for (int mf = 0; mf < 4; mf++)
#pragma unroll
                for (int nf = 0; nf < 4; nf++)
                    mma_f16(acc[mf][nf], af[mf], bf[nf]);
        }
        __syncthreads();
    }

    // epilogue
#pragma unroll
    for (int mf = 0; mf < 4; mf++) {
#pragma unroll
        for (int half = 0; half < 2; half++) {
            const int m = bm + wm * 64 + mf * 16 + lr + half * 8;
#pragma unroll
            for (int nf = 0; nf < 4; nf++) {
                const int n = bn + wn * 32 + nf * 8 + 2 * lc;
                float c0 = acc[mf][nf][half * 2], c1 = acc[mf][nf][half * 2 + 1];
                if (MODE == 0) {
                    float* C = (float*)Cv;
                    *(float2*)&C[(size_t)m * DMODEL + n] = make_float2(c0, c1);
                } else if (MODE == 1) {
                    __half* C = (__half*)Cv;
                    const int b = m >> 11, t = m & 2047;
                    const int h = n >> 6;
                    const int hd = n & 63;
                    const int offd = (hd & ~15) + 2 * islot((hd & 15) >> 1);
                    __half2 hv = __floats2half2_rn(c0 * scale, c1 * scale);
                    *(__half2*)&C[(((size_t)(b * NHEADS + h) * TQ + t) << 6) + offd] = hv;
                } else {
                    __half* C = (__half*)Cv;
                    const int b = m >> 11, t = m & 2047;
                    const int h = n >> 6;
                    const int hd0 = n & 63;
                    const int col = (t & ~15) + 2 * islot((t & 15) >> 1) + (t & 1);
                    __half* base = &C[((size_t)(b * NHEADS + h) * HDIM) * (size_t)TK];
                    base[(size_t)hd0 * TK + col]       = __float2half_rn(c0);
                    base[(size_t)(hd0 + 1) * TK + col] = __float2half_rn(c1);
                }
            }
        }
    }
}

// ---------------- fused attention, fp16 mma, 2 m-tiles per warp -----------------
// AQ=128 q-rows, 4 warps x 32 rows (2 m16 tiles); KT=64 keys; K double-buffered,
// V^T single-buffered overlapped; Q fragments hoisted (fp16: only 32 regs).
#define AQ   128
#define KT   64
#define ASTR 80   // halves; conflict-free LDS.64

__global__ void __launch_bounds__(128, 2)
attn_h16(const __half* __restrict__ Q, const __half* __restrict__ K,
         const __half* __restrict__ V, const __half* __restrict__ mask,
         const unsigned char* __restrict__ kpm, __half* __restrict__ O)
{
    extern __shared__ __half smh[];
    __half* Qs = smh;                      // 128 x 80
    __half* Ks = smh + AQ * ASTR;          // [2][64][80]
    __half* Vs = Ks + 2 * KT * ASTR;       // 64 x 80 (V^T)

    const int tid  = threadIdx.x;
    const int lane = tid & 31;
    const int warp = tid >> 5;
    const int lr   = lane >> 2;
    const int lc   = lane & 3;

    const int q0 = blockIdx.x * AQ;
    const int bh = blockIdx.y;
    const int b  = bh >> 4;
    const int h  = bh & 15;

    const __half* Qb = Q + (size_t)bh * TQ * HDIM;
    const __half* Kb = K + (size_t)bh * TK * HDIM;
    const __half* Vb = V + (size_t)bh * HDIM * TK;

    // stage Q tile (128 rows x 64 halves = 1024 cp16)
#pragma unroll
    for (int r = 0; r < 8; r++) {
        int id = tid + r * 128;
        int row = id >> 3, c8 = (id & 7) * 8;
        cp16(&Qs[row * ASTR + c8], &Qb[(size_t)(q0 + row) * HDIM + c8]);
    }
    asm volatile("cp.async.commit_group;");

    auto cp_K = [&](int st, int kt) {
        const int k0 = kt * KT;
#pragma unroll
        for (int r = 0; r < 4; r++) {
            int id = tid + r * 128;
            int row = id >> 3, c8 = (id & 7) * 8;
            cp16(&Ks[st * KT * ASTR + row * ASTR + c8], &Kb[(size_t)(k0 + row) * HDIM + c8]);
        }
        asm volatile("cp.async.commit_group;");
    };
    auto cp_V = [&](int kt) {
        const int k0 = kt * KT;
#pragma unroll
        for (int r = 0; r < 4; r++) {
            int id = tid + r * 128;
            int row = id >> 3, c8 = (id & 7) * 8;
            cp16(&Vs[row * ASTR + c8], &Vb[(size_t)row * TK + k0 + c8]);
        }
        asm volatile("cp.async.commit_group;");
    };

    cp_K(0, 0);
    asm volatile("cp.async.wait_group 0;");
    __syncthreads();

    // hoist Q fragments: 2 m-tiles x 4 k16 blocks (fp16 -> 32 regs)
    unsigned qf[2][4][4];
#pragma unroll
    for (int mt = 0; mt < 2; mt++)
#pragma unroll
        for (int kk = 0; kk < 4; kk++) {
            const int row = warp * 32 + mt * 16 + lr;
            uint2 u0 = *(const uint2*)&Qs[row * ASTR + kk * 16 + 4 * lc];
            uint2 u1 = *(const uint2*)&Qs[(row + 8) * ASTR + kk * 16 + 4 * lc];
            qf[mt][kk][0] = u0.x; qf[mt][kk][1] = u1.x;
            qf[mt][kk][2] = u0.y; qf[mt][kk][3] = u1.y;
        }

    float m_i[2][2], l_i[2][2], o[2][8][4];
#pragma unroll
    for (int mt = 0; mt < 2; mt++) {
#pragma unroll
        for (int hf = 0; hf < 2; hf++) { m_i[mt][hf] = -INFINITY; l_i[mt][hf] = 0.f; }
#pragma unroll
        for (int nf = 0; nf < 8; nf++)
#pragma unroll
            for (int c = 0; c < 4; c++) o[mt][nf][c] = 0.f;
    }

    const int NT = TK / KT;   // 32
    for (int kt = 0; kt < NT; kt++) {
        const int k0 = kt * KT;

        cp_V(kt);
        if (kt + 1 < NT) cp_K((kt + 1) & 1, kt + 1);
        if (kt + 1 < NT) asm volatile("cp.async.wait_group 2;");
        else             asm volatile("cp.async.wait_group 1;");
        __syncthreads();

        const __half* Kst = &Ks[(kt & 1) * KT * ASTR];

        // S = Q @ K^T (B-fragments reused across both m-tiles)
        float s[2][8][4];
#pragma unroll
        for (int mt = 0; mt < 2; mt++)
#pragma unroll
            for (int nf = 0; nf < 8; nf++)
#pragma unroll
                for (int c = 0; c < 4; c++) s[mt][nf][c] = 0.f;

#pragma unroll
        for (int kk = 0; kk < 4; kk++) {
#pragma unroll
            for (int nf = 0; nf < 8; nf++) {
                unsigned bf[2];
                uint2 u = *(const uint2*)&Kst[(nf * 8 + lr) * ASTR + kk * 16 + 4 * lc];
                bf[0] = u.x; bf[1] = u.y;
                mma_f16(s[0][nf], qf[0][kk], bf);
                mma_f16(s[1][nf], qf[1][kk], bf);
            }
        }

        // key padding flags (shared by both m-tiles)
        uchar2 kp[8];
#pragma unroll
        for (int nf = 0; nf < 8; nf++)
            kp[nf] = *(const uchar2*)&kpm[(size_t)b * TK + k0 + nf * 8 + 2 * lc];

        // masks + online softmax
#pragma unroll
        for (int mt = 0; mt < 2; mt++) {
#pragma unroll
            for (int hf = 0; hf < 2; hf++) {
                const int qg = q0 + warp * 32 + mt * 16 + lr + hf * 8;
                const __half* mrow = &mask[(size_t)qg * TK + k0];
                float mx = -INFINITY;
#pragma unroll
                for (int nf = 0; nf < 8; nf++) {
                    float2 mv = __half22float2(*(const __half2*)&mrow[nf * 8 + 2 * lc]);
                    float v0 = s[mt][nf][hf * 2]     + mv.x;
                    float v1 = s[mt][nf][hf * 2 + 1] + mv.y;
                    if (kp[nf].x) v0 = -INFINITY;
                    if (kp[nf].y) v1 = -INFINITY;
                    s[mt][nf][hf * 2]     = v0;
                    s[mt][nf][hf * 2 + 1] = v1;
                    mx = fmaxf(mx, fmaxf(v0, v1));
                }
                mx = fmaxf(mx, __shfl_xor_sync(0xffffffffu, mx, 1));
                mx = fmaxf(mx, __shfl_xor_sync(0xffffffffu, mx, 2));
                float mnew = fmaxf(m_i[mt][hf], mx);
                float alpha, rs = 0.f;
                if (mnew == -INFINITY) {
                    alpha = 1.f;
#pragma unroll
                    for (int nf = 0; nf < 8; nf++) {
                        s[mt][nf][hf * 2] = 0.f;
                        s[mt][nf][hf * 2 + 1] = 0.f;
                    }
                } else {
                    alpha = (m_i[mt][hf] == -INFINITY) ? 0.f : __expf(m_i[mt][hf] - mnew);
#pragma unroll
                    for (int nf = 0; nf < 8; nf++) {
                        float p0 = __expf(s[mt][nf][hf * 2]     - mnew);
                        float p1 = __expf(s[mt][nf][hf * 2 + 1] - mnew);
                        s[mt][nf][hf * 2]     = p0;
                        s[mt][nf][hf * 2 + 1] = p1;
                        rs += p0 + p1;
                    }
                }
                rs += __shfl_xor_sync(0xffffffffu, rs, 1);
                rs += __shfl_xor_sync(0xffffffffu, rs, 2);
                l_i[mt][hf] = l_i[mt][hf] * alpha + rs;
                m_i[mt][hf] = mnew;
#pragma unroll
                for (int nf = 0; nf < 8; nf++) {
                    o[mt][nf][hf * 2]     *= alpha;
                    o[mt][nf][hf * 2 + 1] *= alpha;
                }
            }
        }

        // V ready
        if (kt + 1 < NT) asm volatile("cp.async.wait_group 1;");
        else             asm volatile("cp.async.wait_group 0;");
        __syncthreads();

        // O += P @ V : P fragments built in registers; V-fragments reused across m-tiles
#pragma unroll
        for (int kb = 0; kb < 4; kb++) {
            unsigned af[2][4];
#pragma unroll
            for (int mt = 0; mt < 2; mt++) {
                af[mt][0] = pack_h2(s[mt][2 * kb][0],     s[mt][2 * kb][1]);
                af[mt][1] = pack_h2(s[mt][2 * kb][2],     s[mt][2 * kb][3]);
                af[mt][2] = pack_h2(s[mt][2 * kb + 1][0], s[mt][2 * kb + 1][1]);
                af[mt][3] = pack_h2(s[mt][2 * kb + 1][2], s[mt][2 * kb + 1][3]);
            }
#pragma unroll
            for (int nf = 0; nf < 8; nf++) {
                unsigned bf[2];
                uint2 u = *(const uint2*)&Vs[(nf * 8 + lr) * ASTR + kb * 16 + 4 * lc];
                bf[0] = u.x; bf[1] = u.y;
                mma_f16(o[0][nf], af[0], bf);
                mma_f16(o[1][nf], af[1], bf);
            }
        }
        __syncthreads();
    }

    // finalize: (b,t,dmodel-interleaved) fp16 (consumed by final GEMM)
#pragma unroll
    for (int mt = 0; mt < 2; mt++)
#pragma unroll
        for (int hf = 0; hf < 2; hf++) {
            const float inv = (l_i[mt][hf] > 0.f) ? (1.f / l_i[mt][hf]) : 0.f;
            const int t = q0 + warp * 32 + mt * 16 + lr + hf * 8;
#pragma unroll
            for (int nf = 0; nf < 8; nf++) {
                const int n = h * HDIM + nf * 8 + 2 * lc;
                const int offd = (n & ~15) + 2 * islot((n & 15) >> 1);
                __half2 hv = __floats2half2_rn(o[mt][nf][hf * 2] * inv,
                                               o[mt][nf][hf * 2 + 1] * inv);
                *(__half2*)&O[((size_t)(b * TQ + t)) * DMODEL + offd] = hv;
            }
        }
}

// ---------------- launch --------------------------------------------------------
extern "C" void kernel_launch(void* const* d_in, const int* in_sizes, int n_in,
                              void* d_out, int out_size)
{
    const float* x_q   = (const float*)d_in[0];
    const float* x_kv  = (const float*)d_in[1];
    const float* amask = (const float*)d_in[2];
    const unsigned char* kpm = (const unsigned char*)d_in[3];
    const float* Wq = (const float*)d_in[4];
    const float* Wk = (const float*)d_in[5];
    const float* Wv = (const float*)d_in[6];
    const float* Wo = (const float*)d_in[7];
    float* out = (float*)d_out;

    __half *qP, *kP, *vP, *oP, *xqP, *xkvP, *wqP, *wkP, *wvP, *woP, *mP;
    cudaGetSymbolAddress((void**)&qP,  h_Q);
    cudaGetSymbolAddress((void**)&kP,  h_K);
    cudaGetSymbolAddress((void**)&vP,  h_V);
    cudaGetSymbolAddress((void**)&oP,  h_O);
    cudaGetSymbolAddress((void**)&xqP, h_Xq);
    cudaGetSymbolAddress((void**)&xkvP,h_Xkv);
    cudaGetSymbolAddress((void**)&wqP, h_Wq);
    cudaGetSymbolAddress((void**)&wkP, h_Wk);
    cudaGetSymbolAddress((void**)&wvP, h_Wv);
    cudaGetSymbolAddress((void**)&woP, h_Wo);
    cudaGetSymbolAddress((void**)&mP,  h_Mask);

    const int NX = MROWS * DMODEL;   // 8M
    const int NW = DMODEL * DMODEL;  // 1M
    const int NM = TQ * TK;          // 4M
    cvt_h16_kernel<<<NX / 8 / 256, 256>>>(x_q,  xqP,  NX, 1.0f);
    cvt_h16_kernel<<<NX / 8 / 256, 256>>>(x_kv, xkvP, NX, 1.0f);
    cvt_h16_kernel<<<NW / 8 / 256, 256>>>(Wq, wqP, NW, 1.0f);
    cvt_h16_kernel<<<NW / 8 / 256, 256>>>(Wk, wkP, NW, 1.0f);
    cvt_h16_kernel<<<NW / 8 / 256, 256>>>(Wv, wvP, NW, 1.0f);
    cvt_h16_kernel<<<NW / 8 / 256, 256>>>(Wo, woP, NW, 1.0f);
    cvt_mask_kernel<<<NM / 8 / 256, 256>>>(amask, mP, NM);

    const int gemm_smem = 2 * (BM + BN) * GST * (int)sizeof(__half);   // 81920
    cudaFuncSetAttribute(gemm_h16<0>, cudaFuncAttributeMaxDynamicSharedMemorySize, gemm_smem);
    cudaFuncSetAttribute(gemm_h16<1>, cudaFuncAttributeMaxDynamicSharedMemorySize, gemm_smem);
    cudaFuncSetAttribute(gemm_h16<2>, cudaFuncAttributeMaxDynamicSharedMemorySize, gemm_smem);

    dim3 gblk(DMODEL / BN, MROWS / BM);   // (8, 64)
    gemm_h16<1><<<gblk, 256, gemm_smem>>>(xqP,  wqP, qP, 0.125f);
    gemm_h16<1><<<gblk, 256, gemm_smem>>>(xkvP, wkP, kP, 1.0f);
    gemm_h16<2><<<gblk, 256, gemm_smem>>>(xkvP, wvP, vP, 1.0f);

    const int attn_smem = (AQ * ASTR + 3 * KT * ASTR) * (int)sizeof(__half);   // 51200
    cudaFuncSetAttribute(attn_h16, cudaFuncAttributeMaxDynamicSharedMemorySize, attn_smem);
    dim3 ga(TQ / AQ, BATCH * NHEADS);     // (16, 64)
    attn_h16<<<ga, 128, attn_smem>>>(qP, kP, vP, mP, kpm, oP);

    gemm_h16<0><<<gblk, 256, gemm_smem>>>(oP, woP, out, 1.0f);
}

// round 10
// speedup vs baseline: 1.0766x; 1.0766x over previous
#include <cuda_runtime.h>
#include <cuda_fp16.h>
#include <math.h>

#define BATCH   4
#define TQ      2048
#define TK      2048
#define DMODEL  1024
#define NHEADS  16
#define HDIM    64
#define MROWS   (BATCH * TQ)   // 8192

// ---------------- scratch (__device__ globals; no allocation allowed) -------
// "interleaved" = within each 16-element k-block, pair j at slot (j<4?2j:2j-7)
// so every mma.sync fp16 fragment is a single LDS.64.
__device__ __half h_Q[MROWS * DMODEL];   // (b,h,t,hd-interleaved), prescaled 1/8
__device__ __half h_K[MROWS * DMODEL];   // (b,h,t,hd-interleaved)
__device__ __half h_V[MROWS * DMODEL];   // (b,h,hd,t-interleaved)  (V^T)
__device__ __half h_O[MROWS * DMODEL];   // (b,t,dmodel-interleaved)
__device__ __half h_Xq[MROWS * DMODEL];  // x_q  interleaved
__device__ __half h_Xkv[MROWS * DMODEL]; // x_kv interleaved
__device__ __half h_Wq[DMODEL * DMODEL];
__device__ __half h_Wk[DMODEL * DMODEL];
__device__ __half h_Wv[DMODEL * DMODEL];
__device__ __half h_Wo[DMODEL * DMODEL];
__device__ __half h_Mask[TQ * TK];       // additive mask, fp16

// ---------------- helpers ----------------------------------------------------
__device__ __forceinline__ void mma_f16(float* d, const unsigned* a, const unsigned* b) {
    asm volatile(
        "mma.sync.aligned.m16n8k16.row.col.f32.f16.f16.f32 "
        "{%0,%1,%2,%3}, {%4,%5,%6,%7}, {%8,%9}, {%0,%1,%2,%3};"
        : "+f"(d[0]), "+f"(d[1]), "+f"(d[2]), "+f"(d[3])
        : "r"(a[0]), "r"(a[1]), "r"(a[2]), "r"(a[3]), "r"(b[0]), "r"(b[1]));
}

__device__ __forceinline__ unsigned pack_h2(float lo, float hi) {
    __half2 h = __floats2half2_rn(lo, hi);
    return *(unsigned*)&h;
}

__device__ __forceinline__ void cp16(void* smem_dst, const void* gmem_src) {
    unsigned s = (unsigned)__cvta_generic_to_shared(smem_dst);
    asm volatile("cp.async.cg.shared.global [%0], [%1], 16;" :: "r"(s), "l"(gmem_src));
}

__device__ __forceinline__ int islot(int j) { return (j < 4) ? 2 * j : 2 * j - 7; }

// ---------------- pre-convert: fp32 -> fp16, k-pair-interleaved ---------------
__device__ __forceinline__ void cvt_body(const float* __restrict__ src,
                                         __half* __restrict__ dst, int i8, float scale)
{
    float4 v0 = *(const float4*)&src[i8];
    float4 v1 = *(const float4*)&src[i8 + 4];
    int base2 = (i8 & ~15) >> 1;
    int hi = (i8 & 15) ? 1 : 0;
    __half2* d = (__half2*)dst;
    d[base2 + 0 + hi] = __floats2half2_rn(v0.x * scale, v0.y * scale);
    d[base2 + 2 + hi] = __floats2half2_rn(v0.z * scale, v0.w * scale);
    d[base2 + 4 + hi] = __floats2half2_rn(v1.x * scale, v1.y * scale);
    d[base2 + 6 + hi] = __floats2half2_rn(v1.z * scale, v1.w * scale);
}

__global__ void cvt_h16_kernel(const float* __restrict__ src, __half* __restrict__ dst,
                               int n, float scale)
{
    int i8 = (blockIdx.x * blockDim.x + threadIdx.x) * 8;
    if (i8 >= n) return;
    cvt_body(src, dst, i8, scale);
}

// fused 4-weight conversion (one launch)
__global__ void cvt_w4_kernel(const float* w0, const float* w1,
                              const float* w2, const float* w3,
                              __half* d0, __half* d1, __half* d2, __half* d3, int n)
{
    int i8 = (blockIdx.x * blockDim.x + threadIdx.x) * 8;
    if (i8 >= n) return;
    const float* s; __half* d;
    switch (blockIdx.y) {
        case 0: s = w0; d = d0; break;
        case 1: s = w1; d = d1; break;
        case 2: s = w2; d = d2; break;
        default: s = w3; d = d3; break;
    }
    cvt_body(s, d, i8, 1.0f);
}

// plain fp32 -> fp16 (for the additive mask)
__global__ void cvt_mask_kernel(const float* __restrict__ src, __half* __restrict__ dst, int n) {
    int i8 = (blockIdx.x * blockDim.x + threadIdx.x) * 8;
    if (i8 >= n) return;
    float4 v0 = *(const float4*)&src[i8];
    float4 v1 = *(const float4*)&src[i8 + 4];
    __half2 h[4];
    h[0] = __floats2half2_rn(v0.x, v0.y);
    h[1] = __floats2half2_rn(v0.z, v0.w);
    h[2] = __floats2half2_rn(v1.x, v1.y);
    h[3] = __floats2half2_rn(v1.z, v1.w);
    *(uint4*)&dst[i8] = *(uint4*)h;
}

// ---------------- fp16 GEMM: C = A(M,K) @ W(N,K)^T ----------------------------
// 128x128x64 block, 256 threads, 8 warps of 64x32, cp.async double buffer.
#define BM   128
#define BN   128
#define BKH  64
#define GST  80     // halves; 40 words = 8 mod 32 -> conflict-free LDS.64

template <int MODE>
__global__ void __launch_bounds__(256, 2)
gemm_h16(const __half* __restrict__ A, const __half* __restrict__ W,
         void* __restrict__ Cv, float scale)
{
    extern __shared__ __half smh[];
    __half* As = smh;                      // [2][BM][GST]
    __half* Ws = smh + 2 * BM * GST;       // [2][BN][GST]

    const int tid  = threadIdx.x;
    const int lane = tid & 31;
    const int warp = tid >> 5;
    const int wm   = warp >> 2;
    const int wn   = warp & 3;
    const int bm   = blockIdx.y * BM;
    const int bn   = blockIdx.x * BN;
    const int lr   = lane >> 2;
    const int lc   = lane & 3;

    float acc[4][4][4];
#pragma unroll
    for (int i = 0; i < 4; i++)
#pragma unroll
        for (int j = 0; j < 4; j++)
#pragma unroll
            for (int c = 0; c < 4; c++) acc[i][j][c] = 0.f;

    const int NIT = DMODEL / BKH;  // 16

    auto load_stage = [&](int st, int k0) {
#pragma unroll
        for (int r = 0; r < 4; r++) {
            int id  = tid + r * 256;
            int m   = id >> 3;
            int c8  = (id & 7) * 8;
            cp16(&As[(st * BM + m) * GST + c8], &A[(size_t)(bm + m) * DMODEL + k0 + c8]);
        }
#pragma unroll
        for (int r = 0; r < 4; r++) {
            int id  = tid + r * 256;
            int m   = id >> 3;
            int c8  = (id & 7) * 8;
            cp16(&Ws[(st * BN + m) * GST + c8], &W[(size_t)(bn + m) * DMODEL + k0 + c8]);
        }
        asm volatile("cp.async.commit_group;");
    };

    load_stage(0, 0);

    for (int it = 0; it < NIT; it++) {
        if (it + 1 < NIT) {
            load_stage((it + 1) & 1, (it + 1) * BKH);
            asm volatile("cp.async.wait_group 1;");
        } else {
            asm volatile("cp.async.wait_group 0;");
        }
        __syncthreads();
        const __half* Ab = &As[(it & 1) * BM * GST];
        const __half* Wb = &Ws[(it & 1) * BN * GST];

#pragma unroll
        for (int kk = 0; kk < 4; kk++) {
            unsigned af[4][4], bf[4][2];
#pragma unroll
            for (int mf = 0; mf < 4; mf++) {
                const int row = wm * 64 + mf * 16 + lr;
                uint2 u0 = *(const uint2*)&Ab[row * GST + kk * 16 + 4 * lc];
                uint2 u1 = *(const uint2*)&Ab[(row + 8) * GST + kk * 16 + 4 * lc];
                af[mf][0] = u0.x; af[mf][1] = u1.x; af[mf][2] = u0.y; af[mf][3] = u1.y;
            }
#pragma unroll
            for (int nf = 0; nf < 4; nf++) {
                const int row = wn * 32 + nf * 8 + lr;
                uint2 u = *(const uint2*)&Wb[row * GST + kk * 16 + 4 * lc];
                bf[nf][0] = u.x; bf[nf][1] = u.y;
            }
#pragma unroll
            for (int mf = 0; mf < 4; mf++)
#pragma unroll
                for (int nf = 0; nf < 4; nf++)
                    mma_f16(acc[mf][nf], af[mf], bf[nf]);
        }
        __syncthreads();
    }

    // epilogue
#pragma unroll
    for (int mf = 0; mf < 4; mf++) {
#pragma unroll
        for (int half = 0; half < 2; half++) {
            const int m = bm + wm * 64 + mf * 16 + lr + half * 8;
#pragma unroll
            for (int nf = 0; nf < 4; nf++) {
                const int n = bn + wn * 32 + nf * 8 + 2 * lc;
                float c0 = acc[mf][nf][half * 2], c1 = acc[mf][nf][half * 2 + 1];
                if (MODE == 0) {
                    float* C = (float*)Cv;
                    *(float2*)&C[(size_t)m * DMODEL + n] = make_float2(c0, c1);
                } else if (MODE == 1) {
                    __half* C = (__half*)Cv;
                    const int b = m >> 11, t = m & 2047;
                    const int h = n >> 6;
                    const int hd = n & 63;
                    const int offd = (hd & ~15) + 2 * islot((hd & 15) >> 1);
                    __half2 hv = __floats2half2_rn(c0 * scale, c1 * scale);
                    *(__half2*)&C[(((size_t)(b * NHEADS + h) * TQ + t) << 6) + offd] = hv;
                } else {
                    __half* C = (__half*)Cv;
                    const int b = m >> 11, t = m & 2047;
                    const int h = n >> 6;
                    const int hd0 = n & 63;
                    const int col = (t & ~15) + 2 * islot((t & 15) >> 1) + (t & 1);
                    __half* base = &C[((size_t)(b * NHEADS + h) * HDIM) * (size_t)TK];
                    base[(size_t)hd0 * TK + col]       = __float2half_rn(c0);
                    base[(size_t)(hd0 + 1) * TK + col] = __float2half_rn(c1);
                }
            }
        }
    }
}

// ---------------- fused attention, fp16 mma ------------------------------------
// 64 q-rows, 4 warps (16 rows each); KT=64 keys; K AND V double-buffered via
// cp.async, prefetched one tile ahead -> ONE wait + ONE sync per tile.
#define AQ   64
#define KT   64
#define ASTR 80   // halves; 40 words = 8 mod 32 -> conflict-free LDS.64

__global__ void __launch_bounds__(128, 3)
attn_h16(const __half* __restrict__ Q, const __half* __restrict__ K,
         const __half* __restrict__ V, const __half* __restrict__ mask,
         const unsigned char* __restrict__ kpm, __half* __restrict__ O)
{
    extern __shared__ __half smh[];
    __half* Qs = smh;                      // 64 x 80
    __half* Ks = smh + AQ * ASTR;          // [2][64][80]
    __half* Vs = Ks + 2 * KT * ASTR;       // [2][64][80] (V^T)

    const int tid  = threadIdx.x;
    const int lane = tid & 31;
    const int warp = tid >> 5;
    const int lr   = lane >> 2;
    const int lc   = lane & 3;

    const int q0 = blockIdx.x * AQ;
    const int bh = blockIdx.y;
    const int b  = bh >> 4;
    const int h  = bh & 15;

    const __half* Qb = Q + (size_t)bh * TQ * HDIM;
    const __half* Kb = K + (size_t)bh * TK * HDIM;
    const __half* Vb = V + (size_t)bh * HDIM * TK;

    // stage Q (group A)
#pragma unroll
    for (int r = 0; r < 4; r++) {
        int id = tid + r * 128;
        int row = id >> 3, c8 = (id & 7) * 8;
        cp16(&Qs[row * ASTR + c8], &Qb[(size_t)(q0 + row) * HDIM + c8]);
    }
    asm volatile("cp.async.commit_group;");

    // combined K+V tile prefetch (one commit group per tile)
    auto cp_KV = [&](int st, int kt) {
        const int k0 = kt * KT;
#pragma unroll
        for (int r = 0; r < 4; r++) {
            int id = tid + r * 128;
            int row = id >> 3, c8 = (id & 7) * 8;
            cp16(&Ks[st * KT * ASTR + row * ASTR + c8], &Kb[(size_t)(k0 + row) * HDIM + c8]);
        }
#pragma unroll
        for (int r = 0; r < 4; r++) {
            int id = tid + r * 128;
            int row = id >> 3, c8 = (id & 7) * 8;   // row = hd
            cp16(&Vs[st * KT * ASTR + row * ASTR + c8], &Vb[(size_t)row * TK + k0 + c8]);
        }
        asm volatile("cp.async.commit_group;");
    };

    cp_KV(0, 0);                           // group B (tile 0)

    // wait for Q (group A); tile-0 group may still be in flight
    asm volatile("cp.async.wait_group 1;");
    __syncthreads();

    unsigned qf[4][4];
#pragma unroll
    for (int kk = 0; kk < 4; kk++) {
        const int row = warp * 16 + lr;
        uint2 u0 = *(const uint2*)&Qs[row * ASTR + kk * 16 + 4 * lc];
        uint2 u1 = *(const uint2*)&Qs[(row + 8) * ASTR + kk * 16 + 4 * lc];
        qf[kk][0] = u0.x; qf[kk][1] = u1.x; qf[kk][2] = u0.y; qf[kk][3] = u1.y;
    }

    float m_i[2] = {-INFINITY, -INFINITY};
    float l_i[2] = {0.f, 0.f};
    float o[8][4];
#pragma unroll
    for (int nf = 0; nf < 8; nf++)
#pragma unroll
        for (int c = 0; c < 4; c++) o[nf][c] = 0.f;

    const int NT = TK / KT;   // 32
    for (int kt = 0; kt < NT; kt++) {
        const int k0 = kt * KT;

        // tile kt's K+V complete; all warps done reading buffer (kt-1)&1
        asm volatile("cp.async.wait_group 0;");
        __syncthreads();

        // prefetch tile kt+1 into the other buffer (overlaps with this tile's compute)
        if (kt + 1 < NT) cp_KV((kt + 1) & 1, kt + 1);

        const __half* Kst = &Ks[(kt & 1) * KT * ASTR];
        const __half* Vst = &Vs[(kt & 1) * KT * ASTR];

        // S = Q @ K^T
        float s[8][4];
#pragma unroll
        for (int nf = 0; nf < 8; nf++)
#pragma unroll
            for (int c = 0; c < 4; c++) s[nf][c] = 0.f;

#pragma unroll
        for (int kk = 0; kk < 4; kk++) {
#pragma unroll
            for (int nf = 0; nf < 8; nf++) {
                unsigned bf[2];
                uint2 u = *(const uint2*)&Kst[(nf * 8 + lr) * ASTR + kk * 16 + 4 * lc];
                bf[0] = u.x; bf[1] = u.y;
                mma_f16(s[nf], qf[kk], bf);
            }
        }

        // masks + online softmax
        uchar2 kp[8];
#pragma unroll
        for (int nf = 0; nf < 8; nf++)
            kp[nf] = *(const uchar2*)&kpm[(size_t)b * TK + k0 + nf * 8 + 2 * lc];

#pragma unroll
        for (int hf = 0; hf < 2; hf++) {
            const int qg = q0 + warp * 16 + lr + hf * 8;
            const __half* mrow = &mask[(size_t)qg * TK + k0];
            float mx = -INFINITY;
#pragma unroll
            for (int nf = 0; nf < 8; nf++) {
                float2 mv = __half22float2(*(const __half2*)&mrow[nf * 8 + 2 * lc]);
                float v0 = s[nf][hf * 2]     + mv.x;
                float v1 = s[nf][hf * 2 + 1] + mv.y;
                if (kp[nf].x) v0 = -INFINITY;
                if (kp[nf].y) v1 = -INFINITY;
                s[nf][hf * 2]     = v0;
                s[nf][hf * 2 + 1] = v1;
                mx = fmaxf(mx, fmaxf(v0, v1));
            }
            mx = fmaxf(mx, __shfl_xor_sync(0xffffffffu, mx, 1));
            mx = fmaxf(mx, __shfl_xor_sync(0xffffffffu, mx, 2));
            float mnew = fmaxf(m_i[hf], mx);
            float alpha, rs = 0.f;
            if (mnew == -INFINITY) {
                alpha = 1.f;
#pragma unroll
                for (int nf = 0; nf < 8; nf++) {
                    s[nf][hf * 2] = 0.f;
                    s[nf][hf * 2 + 1] = 0.f;
                }
            } else {
                alpha = (m_i[hf] == -INFINITY) ? 0.f : __expf(m_i[hf] - mnew);
#pragma unroll
                for (int nf = 0; nf < 8; nf++) {
                    float p0 = __expf(s[nf][hf * 2]     - mnew);
                    float p1 = __expf(s[nf][hf * 2 + 1] - mnew);
                    s[nf][hf * 2]     = p0;
                    s[nf][hf * 2 + 1] = p1;
                    rs += p0 + p1;
                }
            }
            rs += __shfl_xor_sync(0xffffffffu, rs, 1);
            rs += __shfl_xor_sync(0xffffffffu, rs, 2);
            l_i[hf] = l_i[hf] * alpha + rs;
            m_i[hf] = mnew;
#pragma unroll
            for (int nf = 0; nf < 8; nf++) {
                o[nf][hf * 2]     *= alpha;
                o[nf][hf * 2 + 1] *= alpha;
            }
        }

        // O += P @ V : P fragments built in registers (V already resident)
#pragma unroll
        for (int kb = 0; kb < 4; kb++) {
            unsigned af[4];
            af[0] = pack_h2(s[2 * kb][0],     s[2 * kb][1]);
            af[1] = pack_h2(s[2 * kb][2],     s[2 * kb][3]);
            af[2] = pack_h2(s[2 * kb + 1][0], s[2 * kb + 1][1]);
            af[3] = pack_h2(s[2 * kb + 1][2], s[2 * kb + 1][3]);
#pragma unroll
            for (int nf = 0; nf < 8; nf++) {
                unsigned bf[2];
                uint2 u = *(const uint2*)&Vst[(nf * 8 + lr) * ASTR + kb * 16 + 4 * lc];
                bf[0] = u.x; bf[1] = u.y;
                mma_f16(o[nf], af, bf);
            }
        }
    }

    // finalize: (b,t,dmodel-interleaved) fp16 (consumed by final GEMM)
#pragma unroll
    for (int hf = 0; hf < 2; hf++) {
        const float inv = (l_i[hf] > 0.f) ? (1.f / l_i[hf]) : 0.f;
        const int t = q0 + warp * 16 + lr + hf * 8;
#pragma unroll
        for (int nf = 0; nf < 8; nf++) {
            const int n = h * HDIM + nf * 8 + 2 * lc;
            const int offd = (n & ~15) + 2 * islot((n & 15) >> 1);
            __half2 hv = __floats2half2_rn(o[nf][hf * 2] * inv, o[nf][hf * 2 + 1] * inv);
            *(__half2*)&O[((size_t)(b * TQ + t)) * DMODEL + offd] = hv;
        }
    }
}

// ---------------- launch --------------------------------------------------------
extern "C" void kernel_launch(void* const* d_in, const int* in_sizes, int n_in,
                              void* d_out, int out_size)
{
    const float* x_q   = (const float*)d_in[0];
    const float* x_kv  = (const float*)d_in[1];
    const float* amask = (const float*)d_in[2];
    const unsigned char* kpm = (const unsigned char*)d_in[3];
    const float* Wq = (const float*)d_in[4];
    const float* Wk = (const float*)d_in[5];
    const float* Wv = (const float*)d_in[6];
    const float* Wo = (const float*)d_in[7];
    float* out = (float*)d_out;

    __half *qP, *kP, *vP, *oP, *xqP, *xkvP, *wqP, *wkP, *wvP, *woP, *mP;
    cudaGetSymbolAddress((void**)&qP,  h_Q);
    cudaGetSymbolAddress((void**)&kP,  h_K);
    cudaGetSymbolAddress((void**)&vP,  h_V);
    cudaGetSymbolAddress((void**)&oP,  h_O);
    cudaGetSymbolAddress((void**)&xqP, h_Xq);
    cudaGetSymbolAddress((void**)&xkvP,h_Xkv);
    cudaGetSymbolAddress((void**)&wqP, h_Wq);
    cudaGetSymbolAddress((void**)&wkP, h_Wk);
    cudaGetSymbolAddress((void**)&wvP, h_Wv);
    cudaGetSymbolAddress((void**)&woP, h_Wo);
    cudaGetSymbolAddress((void**)&mP,  h_Mask);

    const int NX = MROWS * DMODEL;   // 8M
    const int NW = DMODEL * DMODEL;  // 1M
    const int NM = TQ * TK;          // 4M
    cvt_h16_kernel<<<NX / 8 / 256, 256>>>(x_q,  xqP,  NX, 1.0f);
    cvt_h16_kernel<<<NX / 8 / 256, 256>>>(x_kv, xkvP, NX, 1.0f);
    dim3 gw(NW / 8 / 256, 4);
    cvt_w4_kernel<<<gw, 256>>>(Wq, Wk, Wv, Wo, wqP, wkP, wvP, woP, NW);
    cvt_mask_kernel<<<NM / 8 / 256, 256>>>(amask, mP, NM);

    const int gemm_smem = 2 * (BM + BN) * GST * (int)sizeof(__half);   // 81920
    cudaFuncSetAttribute(gemm_h16<0>, cudaFuncAttributeMaxDynamicSharedMemorySize, gemm_smem);
    cudaFuncSetAttribute(gemm_h16<1>, cudaFuncAttributeMaxDynamicSharedMemorySize, gemm_smem);
    cudaFuncSetAttribute(gemm_h16<2>, cudaFuncAttributeMaxDynamicSharedMemorySize, gemm_smem);

    dim3 gblk(DMODEL / BN, MROWS / BM);   // (8, 64)
    gemm_h16<1><<<gblk, 256, gemm_smem>>>(xqP,  wqP, qP, 0.125f);
    gemm_h16<1><<<gblk, 256, gemm_smem>>>(xkvP, wkP, kP, 1.0f);
    gemm_h16<2><<<gblk, 256, gemm_smem>>>(xkvP, wvP, vP, 1.0f);

    const int attn_smem = 5 * KT * ASTR * (int)sizeof(__half);   // 51200
    cudaFuncSetAttribute(attn_h16, cudaFuncAttributeMaxDynamicSharedMemorySize, attn_smem);
    dim3 ga(TQ / AQ, BATCH * NHEADS);     // (32, 64)
    attn_h16<<<ga, 128, attn_smem>>>(qP, kP, vP, mP, kpm, oP);

    gemm_h16<0><<<gblk, 256, gemm_smem>>>(oP, woP, out, 1.0f);
}

// round 11
// speedup vs baseline: 1.3170x; 1.2232x over previous
#include <cuda_runtime.h>
#include <cuda_fp16.h>
#include <math.h>

#define BATCH   4
#define TQ      2048
#define TK      2048
#define DMODEL  1024
#define NHEADS  16
#define HDIM    64
#define MROWS   (BATCH * TQ)   // 8192

// ---------------- scratch (__device__ globals; no allocation allowed) -------
__device__ __half h_Q[MROWS * DMODEL];   // (b,h,t,hd-interleaved), prescaled 1/8
__device__ __half h_K[MROWS * DMODEL];   // (b,h,t,hd-interleaved)
__device__ __half h_V[MROWS * DMODEL];   // (b,h,hd,t-interleaved)  (V^T)
__device__ __half h_O[MROWS * DMODEL];   // (b,t,dmodel-interleaved)
__device__ __half h_Xq[MROWS * DMODEL];
__device__ __half h_Xkv[MROWS * DMODEL];
__device__ __half h_Wq[DMODEL * DMODEL];
__device__ __half h_Wk[DMODEL * DMODEL];
__device__ __half h_Wv[DMODEL * DMODEL];
__device__ __half h_Wo[DMODEL * DMODEL];
__device__ __half h_Mask[TQ * TK];       // additive mask, fp16
__device__ int    g_flags;               // bit0: mask nonzero, bit1: kpm nonzero

// ---------------- helpers ----------------------------------------------------
__device__ __forceinline__ void mma_f16(float* d, const unsigned* a, const unsigned* b) {
    asm volatile(
        "mma.sync.aligned.m16n8k16.row.col.f32.f16.f16.f32 "
        "{%0,%1,%2,%3}, {%4,%5,%6,%7}, {%8,%9}, {%0,%1,%2,%3};"
        : "+f"(d[0]), "+f"(d[1]), "+f"(d[2]), "+f"(d[3])
        : "r"(a[0]), "r"(a[1]), "r"(a[2]), "r"(a[3]), "r"(b[0]), "r"(b[1]));
}

__device__ __forceinline__ unsigned pack_h2(float lo, float hi) {
    __half2 h = __floats2half2_rn(lo, hi);
    return *(unsigned*)&h;
}

__device__ __forceinline__ void cp16(void* smem_dst, const void* gmem_src) {
    unsigned s = (unsigned)__cvta_generic_to_shared(smem_dst);
    asm volatile("cp.async.cg.shared.global [%0], [%1], 16;" :: "r"(s), "l"(gmem_src));
}

__device__ __forceinline__ int islot(int j) { return (j < 4) ? 2 * j : 2 * j - 7; }

// ---------------- pre-convert kernels ------------------------------------------
__device__ __forceinline__ void cvt_body(const float* __restrict__ src,
                                         __half* __restrict__ dst, int i8, float scale)
{
    float4 v0 = *(const float4*)&src[i8];
    float4 v1 = *(const float4*)&src[i8 + 4];
    int base2 = (i8 & ~15) >> 1;
    int hi = (i8 & 15) ? 1 : 0;
    __half2* d = (__half2*)dst;
    d[base2 + 0 + hi] = __floats2half2_rn(v0.x * scale, v0.y * scale);
    d[base2 + 2 + hi] = __floats2half2_rn(v0.z * scale, v0.w * scale);
    d[base2 + 4 + hi] = __floats2half2_rn(v1.x * scale, v1.y * scale);
    d[base2 + 6 + hi] = __floats2half2_rn(v1.z * scale, v1.w * scale);
}

__global__ void reset_flags_kernel(int* flags) { *flags = 0; }

__global__ void cvt_h16_kernel(const float* __restrict__ src, __half* __restrict__ dst,
                               int n, float scale)
{
    int i8 = (blockIdx.x * blockDim.x + threadIdx.x) * 8;
    if (i8 >= n) return;
    cvt_body(src, dst, i8, scale);
}

__global__ void cvt_w4_kernel(const float* w0, const float* w1,
                              const float* w2, const float* w3,
                              __half* d0, __half* d1, __half* d2, __half* d3, int n)
{
    int i8 = (blockIdx.x * blockDim.x + threadIdx.x) * 8;
    if (i8 >= n) return;
    const float* s; __half* d;
    switch (blockIdx.y) {
        case 0: s = w0; d = d0; break;
        case 1: s = w1; d = d1; break;
        case 2: s = w2; d = d2; break;
        default: s = w3; d = d3; break;
    }
    cvt_body(s, d, i8, 1.0f);
}

// mask fp32 -> fp16 + nonzero detection
__global__ void cvt_mask_kernel(const float* __restrict__ src, __half* __restrict__ dst,
                                int n, int* flags)
{
    int i8 = (blockIdx.x * blockDim.x + threadIdx.x) * 8;
    if (i8 >= n) return;
    float4 v0 = *(const float4*)&src[i8];
    float4 v1 = *(const float4*)&src[i8 + 4];
    __half2 h[4];
    h[0] = __floats2half2_rn(v0.x, v0.y);
    h[1] = __floats2half2_rn(v0.z, v0.w);
    h[2] = __floats2half2_rn(v1.x, v1.y);
    h[3] = __floats2half2_rn(v1.z, v1.w);
    *(uint4*)&dst[i8] = *(uint4*)h;
    bool nz = (v0.x != 0.f) | (v0.y != 0.f) | (v0.z != 0.f) | (v0.w != 0.f) |
              (v1.x != 0.f) | (v1.y != 0.f) | (v1.z != 0.f) | (v1.w != 0.f);
    if (__ballot_sync(0xffffffffu, nz)) {
        if ((threadIdx.x & 31) == 0) atomicOr(flags, 1);
    }
}

// key_padding_mask any-true detection (BATCH*TK bytes)
__global__ void kpm_check_kernel(const unsigned char* __restrict__ kpm, int n, int* flags)
{
    int i16 = (blockIdx.x * blockDim.x + threadIdx.x) * 16;
    if (i16 >= n) return;
    uint4 v = *(const uint4*)&kpm[i16];
    bool nz = (v.x | v.y | v.z | v.w) != 0u;
    if (__ballot_sync(0xffffffffu, nz)) {
        if ((threadIdx.x & 31) == 0) atomicOr(flags, 2);
    }
}

// ---------------- fp16 GEMM: C = A(M,K) @ W(N,K)^T ----------------------------
#define BM   128
#define BN   128
#define BKH  64
#define GST  80     // halves; 40 words = 8 mod 32 -> conflict-free LDS.64

template <int MODE>
__global__ void __launch_bounds__(256, 2)
gemm_h16(const __half* __restrict__ A, const __half* __restrict__ W,
         void* __restrict__ Cv, float scale)
{
    extern __shared__ __half smh[];
    __half* As = smh;                      // [2][BM][GST]
    __half* Ws = smh + 2 * BM * GST;       // [2][BN][GST]

    const int tid  = threadIdx.x;
    const int lane = tid & 31;
    const int warp = tid >> 5;
    const int wm   = warp >> 2;
    const int wn   = warp & 3;
    const int bm   = blockIdx.y * BM;
    const int bn   = blockIdx.x * BN;
    const int lr   = lane >> 2;
    const int lc   = lane & 3;

    float acc[4][4][4];
#pragma unroll
    for (int i = 0; i < 4; i++)
#pragma unroll
        for (int j = 0; j < 4; j++)
#pragma unroll
            for (int c = 0; c < 4; c++) acc[i][j][c] = 0.f;

    const int NIT = DMODEL / BKH;  // 16

    auto load_stage = [&](int st, int k0) {
#pragma unroll
        for (int r = 0; r < 4; r++) {
            int id  = tid + r * 256;
            int m   = id >> 3;
            int c8  = (id & 7) * 8;
            cp16(&As[(st * BM + m) * GST + c8], &A[(size_t)(bm + m) * DMODEL + k0 + c8]);
        }
#pragma unroll
        for (int r = 0; r < 4; r++) {
            int id  = tid + r * 256;
            int m   = id >> 3;
            int c8  = (id & 7) * 8;
            cp16(&Ws[(st * BN + m) * GST + c8], &W[(size_t)(bn + m) * DMODEL + k0 + c8]);
        }
        asm volatile("cp.async.commit_group;");
    };

    load_stage(0, 0);

    for (int it = 0; it < NIT; it++) {
        if (it + 1 < NIT) {
            load_stage((it + 1) & 1, (it + 1) * BKH);
            asm volatile("cp.async.wait_group 1;");
        } else {
            asm volatile("cp.async.wait_group 0;");
        }
        __syncthreads();
        const __half* Ab = &As[(it & 1) * BM * GST];
        const __half* Wb = &Ws[(it & 1) * BN * GST];

#pragma unroll
        for (int kk = 0; kk < 4; kk++) {
            unsigned af[4][4], bf[4][2];
#pragma unroll
            for (int mf = 0; mf < 4; mf++) {
                const int row = wm * 64 + mf * 16 + lr;
                uint2 u0 = *(const uint2*)&Ab[row * GST + kk * 16 + 4 * lc];
                uint2 u1 = *(const uint2*)&Ab[(row + 8) * GST + kk * 16 + 4 * lc];
                af[mf][0] = u0.x; af[mf][1] = u1.x; af[mf][2] = u0.y; af[mf][3] = u1.y;
            }
#pragma unroll
            for (int nf = 0; nf < 4; nf++) {
                const int row = wn * 32 + nf * 8 + lr;
                uint2 u = *(const uint2*)&Wb[row * GST + kk * 16 + 4 * lc];
                bf[nf][0] = u.x; bf[nf][1] = u.y;
            }
#pragma unroll
            for (int mf = 0; mf < 4; mf++)
#pragma unroll
                for (int nf = 0; nf < 4; nf++)
                    mma_f16(acc[mf][nf], af[mf], bf[nf]);
        }
        __syncthreads();
    }

    // epilogue
#pragma unroll
    for (int mf = 0; mf < 4; mf++) {
#pragma unroll
        for (int half = 0; half < 2; half++) {
            const int m = bm + wm * 64 + mf * 16 + lr + half * 8;
#pragma unroll
            for (int nf = 0; nf < 4; nf++) {
                const int n = bn + wn * 32 + nf * 8 + 2 * lc;
                float c0 = acc[mf][nf][half * 2], c1 = acc[mf][nf][half * 2 + 1];
                if (MODE == 0) {
                    float* C = (float*)Cv;
                    *(float2*)&C[(size_t)m * DMODEL + n] = make_float2(c0, c1);
                } else if (MODE == 1) {
                    __half* C = (__half*)Cv;
                    const int b = m >> 11, t = m & 2047;
                    const int h = n >> 6;
                    const int hd = n & 63;
                    const int offd = (hd & ~15) + 2 * islot((hd & 15) >> 1);
                    __half2 hv = __floats2half2_rn(c0 * scale, c1 * scale);
                    *(__half2*)&C[(((size_t)(b * NHEADS + h) * TQ + t) << 6) + offd] = hv;
                } else {
                    __half* C = (__half*)Cv;
                    const int b = m >> 11, t = m & 2047;
                    const int h = n >> 6;
                    const int hd0 = n & 63;
                    const int col = (t & ~15) + 2 * islot((t & 15) >> 1) + (t & 1);
                    __half* base = &C[((size_t)(b * NHEADS + h) * HDIM) * (size_t)TK];
                    base[(size_t)hd0 * TK + col]       = __float2half_rn(c0);
                    base[(size_t)(hd0 + 1) * TK + col] = __float2half_rn(c1);
                }
            }
        }
    }
}

// ---------------- fused attention, fp16 mma ------------------------------------
// 64 q-rows, 4 warps (16 rows each); KT=64 keys; K+V double-buffered, one
// wait+sync per tile. Uniform fast path when mask==0 and kpm==false.
#define AQ   64
#define KT   64
#define ASTR 80

__global__ void __launch_bounds__(128, 3)
attn_h16(const __half* __restrict__ Q, const __half* __restrict__ K,
         const __half* __restrict__ V, const __half* __restrict__ mask,
         const unsigned char* __restrict__ kpm, __half* __restrict__ O,
         const int* __restrict__ flagsP)
{
    extern __shared__ __half smh[];
    __half* Qs = smh;                      // 64 x 80
    __half* Ks = smh + AQ * ASTR;          // [2][64][80]
    __half* Vs = Ks + 2 * KT * ASTR;       // [2][64][80] (V^T)

    const int tid  = threadIdx.x;
    const int lane = tid & 31;
    const int warp = tid >> 5;
    const int lr   = lane >> 2;
    const int lc   = lane & 3;

    const int q0 = blockIdx.x * AQ;
    const int bh = blockIdx.y;
    const int b  = bh >> 4;
    const int h  = bh & 15;

    const bool plain = (*flagsP == 0);     // mask==0 and kpm all false

    const __half* Qb = Q + (size_t)bh * TQ * HDIM;
    const __half* Kb = K + (size_t)bh * TK * HDIM;
    const __half* Vb = V + (size_t)bh * HDIM * TK;

    // stage Q (group A)
#pragma unroll
    for (int r = 0; r < 4; r++) {
        int id = tid + r * 128;
        int row = id >> 3, c8 = (id & 7) * 8;
        cp16(&Qs[row * ASTR + c8], &Qb[(size_t)(q0 + row) * HDIM + c8]);
    }
    asm volatile("cp.async.commit_group;");

    auto cp_KV = [&](int st, int kt) {
        const int k0 = kt * KT;
#pragma unroll
        for (int r = 0; r < 4; r++) {
            int id = tid + r * 128;
            int row = id >> 3, c8 = (id & 7) * 8;
            cp16(&Ks[st * KT * ASTR + row * ASTR + c8], &Kb[(size_t)(k0 + row) * HDIM + c8]);
        }
#pragma unroll
        for (int r = 0; r < 4; r++) {
            int id = tid + r * 128;
            int row = id >> 3, c8 = (id & 7) * 8;   // row = hd
            cp16(&Vs[st * KT * ASTR + row * ASTR + c8], &Vb[(size_t)row * TK + k0 + c8]);
        }
        asm volatile("cp.async.commit_group;");
    };

    cp_KV(0, 0);

    asm volatile("cp.async.wait_group 1;");
    __syncthreads();

    unsigned qf[4][4];
#pragma unroll
    for (int kk = 0; kk < 4; kk++) {
        const int row = warp * 16 + lr;
        uint2 u0 = *(const uint2*)&Qs[row * ASTR + kk * 16 + 4 * lc];
        uint2 u1 = *(const uint2*)&Qs[(row + 8) * ASTR + kk * 16 + 4 * lc];
        qf[kk][0] = u0.x; qf[kk][1] = u1.x; qf[kk][2] = u0.y; qf[kk][3] = u1.y;
    }

    float m_i[2] = {-INFINITY, -INFINITY};
    float l_i[2] = {0.f, 0.f};
    float o[8][4];
#pragma unroll
    for (int nf = 0; nf < 8; nf++)
#pragma unroll
        for (int c = 0; c < 4; c++) o[nf][c] = 0.f;

    const int NT = TK / KT;   // 32
    for (int kt = 0; kt < NT; kt++) {
        const int k0 = kt * KT;

        asm volatile("cp.async.wait_group 0;");
        __syncthreads();

        if (kt + 1 < NT) cp_KV((kt + 1) & 1, kt + 1);

        const __half* Kst = &Ks[(kt & 1) * KT * ASTR];
        const __half* Vst = &Vs[(kt & 1) * KT * ASTR];

        // S = Q @ K^T
        float s[8][4];
#pragma unroll
        for (int nf = 0; nf < 8; nf++)
#pragma unroll
            for (int c = 0; c < 4; c++) s[nf][c] = 0.f;

#pragma unroll
        for (int kk = 0; kk < 4; kk++) {
#pragma unroll
            for (int nf = 0; nf < 8; nf++) {
                unsigned bf[2];
                uint2 u = *(const uint2*)&Kst[(nf * 8 + lr) * ASTR + kk * 16 + 4 * lc];
                bf[0] = u.x; bf[1] = u.y;
                mma_f16(s[nf], qf[kk], bf);
            }
        }

        // online softmax
        if (plain) {
            // fast path: no mask, no kpm
#pragma unroll
            for (int hf = 0; hf < 2; hf++) {
                float mx = -INFINITY;
#pragma unroll
                for (int nf = 0; nf < 8; nf++)
                    mx = fmaxf(mx, fmaxf(s[nf][hf * 2], s[nf][hf * 2 + 1]));
                mx = fmaxf(mx, __shfl_xor_sync(0xffffffffu, mx, 1));
                mx = fmaxf(mx, __shfl_xor_sync(0xffffffffu, mx, 2));
                float mnew = fmaxf(m_i[hf], mx);
                float alpha = __expf(m_i[hf] - mnew);   // 0 when m_i == -inf
                float rs = 0.f;
#pragma unroll
                for (int nf = 0; nf < 8; nf++) {
                    float p0 = __expf(s[nf][hf * 2]     - mnew);
                    float p1 = __expf(s[nf][hf * 2 + 1] - mnew);
                    s[nf][hf * 2]     = p0;
                    s[nf][hf * 2 + 1] = p1;
                    rs += p0 + p1;
                }
                rs += __shfl_xor_sync(0xffffffffu, rs, 1);
                rs += __shfl_xor_sync(0xffffffffu, rs, 2);
                l_i[hf] = l_i[hf] * alpha + rs;
                m_i[hf] = mnew;
#pragma unroll
                for (int nf = 0; nf < 8; nf++) {
                    o[nf][hf * 2]     *= alpha;
                    o[nf][hf * 2 + 1] *= alpha;
                }
            }
        } else {
            uchar2 kp[8];
#pragma unroll
            for (int nf = 0; nf < 8; nf++)
                kp[nf] = *(const uchar2*)&kpm[(size_t)b * TK + k0 + nf * 8 + 2 * lc];

#pragma unroll
            for (int hf = 0; hf < 2; hf++) {
                const int qg = q0 + warp * 16 + lr + hf * 8;
                const __half* mrow = &mask[(size_t)qg * TK + k0];
                float mx = -INFINITY;
#pragma unroll
                for (int nf = 0; nf < 8; nf++) {
                    float2 mv = __half22float2(*(const __half2*)&mrow[nf * 8 + 2 * lc]);
                    float v0 = s[nf][hf * 2]     + mv.x;
                    float v1 = s[nf][hf * 2 + 1] + mv.y;
                    if (kp[nf].x) v0 = -INFINITY;
                    if (kp[nf].y) v1 = -INFINITY;
                    s[nf][hf * 2]     = v0;
                    s[nf][hf * 2 + 1] = v1;
                    mx = fmaxf(mx, fmaxf(v0, v1));
                }
                mx = fmaxf(mx, __shfl_xor_sync(0xffffffffu, mx, 1));
                mx = fmaxf(mx, __shfl_xor_sync(0xffffffffu, mx, 2));
                float mnew = fmaxf(m_i[hf], mx);
                float alpha, rs = 0.f;
                if (mnew == -INFINITY) {
                    alpha = 1.f;
#pragma unroll
                    for (int nf = 0; nf < 8; nf++) {
                        s[nf][hf * 2] = 0.f;
                        s[nf][hf * 2 + 1] = 0.f;
                    }
                } else {
                    alpha = (m_i[hf] == -INFINITY) ? 0.f : __expf(m_i[hf] - mnew);
#pragma unroll
                    for (int nf = 0; nf < 8; nf++) {
                        float p0 = __expf(s[nf][hf * 2]     - mnew);
                        float p1 = __expf(s[nf][hf * 2 + 1] - mnew);
                        s[nf][hf * 2]     = p0;
                        s[nf][hf * 2 + 1] = p1;
                        rs += p0 + p1;
                    }
                }
                rs += __shfl_xor_sync(0xffffffffu, rs, 1);
                rs += __shfl_xor_sync(0xffffffffu, rs, 2);
                l_i[hf] = l_i[hf] * alpha + rs;
                m_i[hf] = mnew;
#pragma unroll
                for (int nf = 0; nf < 8; nf++) {
                    o[nf][hf * 2]     *= alpha;
                    o[nf][hf * 2 + 1] *= alpha;
                }
            }
        }

        // O += P @ V
#pragma unroll
        for (int kb = 0; kb < 4; kb++) {
            unsigned af[4];
            af[0] = pack_h2(s[2 * kb][0],     s[2 * kb][1]);
            af[1] = pack_h2(s[2 * kb][2],     s[2 * kb][3]);
            af[2] = pack_h2(s[2 * kb + 1][0], s[2 * kb + 1][1]);
            af[3] = pack_h2(s[2 * kb + 1][2], s[2 * kb + 1][3]);
#pragma unroll
            for (int nf = 0; nf < 8; nf++) {
                unsigned bf[2];
                uint2 u = *(const uint2*)&Vst[(nf * 8 + lr) * ASTR + kb * 16 + 4 * lc];
                bf[0] = u.x; bf[1] = u.y;
                mma_f16(o[nf], af, bf);
            }
        }
    }

    // finalize: (b,t,dmodel-interleaved) fp16
#pragma unroll
    for (int hf = 0; hf < 2; hf++) {
        const float inv = (l_i[hf] > 0.f) ? (1.f / l_i[hf]) : 0.f;
        const int t = q0 + warp * 16 + lr + hf * 8;
#pragma unroll
        for (int nf = 0; nf < 8; nf++) {
            const int n = h * HDIM + nf * 8 + 2 * lc;
            const int offd = (n & ~15) + 2 * islot((n & 15) >> 1);
            __half2 hv = __floats2half2_rn(o[nf][hf * 2] * inv, o[nf][hf * 2 + 1] * inv);
            *(__half2*)&O[((size_t)(b * TQ + t)) * DMODEL + offd] = hv;
        }
    }
}

// ---------------- launch --------------------------------------------------------
extern "C" void kernel_launch(void* const* d_in, const int* in_sizes, int n_in,
                              void* d_out, int out_size)
{
    const float* x_q   = (const float*)d_in[0];
    const float* x_kv  = (const float*)d_in[1];
    const float* amask = (const float*)d_in[2];
    const unsigned char* kpm = (const unsigned char*)d_in[3];
    const float* Wq = (const float*)d_in[4];
    const float* Wk = (const float*)d_in[5];
    const float* Wv = (const float*)d_in[6];
    const float* Wo = (const float*)d_in[7];
    float* out = (float*)d_out;

    __half *qP, *kP, *vP, *oP, *xqP, *xkvP, *wqP, *wkP, *wvP, *woP, *mP;
    int* flagsP;
    cudaGetSymbolAddress((void**)&qP,  h_Q);
    cudaGetSymbolAddress((void**)&kP,  h_K);
    cudaGetSymbolAddress((void**)&vP,  h_V);
    cudaGetSymbolAddress((void**)&oP,  h_O);
    cudaGetSymbolAddress((void**)&xqP, h_Xq);
    cudaGetSymbolAddress((void**)&xkvP,h_Xkv);
    cudaGetSymbolAddress((void**)&wqP, h_Wq);
    cudaGetSymbolAddress((void**)&wkP, h_Wk);
    cudaGetSymbolAddress((void**)&wvP, h_Wv);
    cudaGetSymbolAddress((void**)&woP, h_Wo);
    cudaGetSymbolAddress((void**)&mP,  h_Mask);
    cudaGetSymbolAddress((void**)&flagsP, g_flags);

    const int NX = MROWS * DMODEL;   // 8M
    const int NW = DMODEL * DMODEL;  // 1M
    const int NM = TQ * TK;          // 4M
    reset_flags_kernel<<<1, 1>>>(flagsP);
    cvt_h16_kernel<<<NX / 8 / 256, 256>>>(x_q,  xqP,  NX, 1.0f);
    cvt_h16_kernel<<<NX / 8 / 256, 256>>>(x_kv, xkvP, NX, 1.0f);
    dim3 gw(NW / 8 / 256, 4);
    cvt_w4_kernel<<<gw, 256>>>(Wq, Wk, Wv, Wo, wqP, wkP, wvP, woP, NW);
    cvt_mask_kernel<<<NM / 8 / 256, 256>>>(amask, mP, NM, flagsP);
    kpm_check_kernel<<<(BATCH * TK) / 16 / 256 + 1, 256>>>(kpm, BATCH * TK, flagsP);

    const int gemm_smem = 2 * (BM + BN) * GST * (int)sizeof(__half);   // 81920
    cudaFuncSetAttribute(gemm_h16<0>, cudaFuncAttributeMaxDynamicSharedMemorySize, gemm_smem);
    cudaFuncSetAttribute(gemm_h16<1>, cudaFuncAttributeMaxDynamicSharedMemorySize, gemm_smem);
    cudaFuncSetAttribute(gemm_h16<2>, cudaFuncAttributeMaxDynamicSharedMemorySize, gemm_smem);

    dim3 gblk(DMODEL / BN, MROWS / BM);   // (8, 64)
    gemm_h16<1><<<gblk, 256, gemm_smem>>>(xqP,  wqP, qP, 0.125f);
    gemm_h16<1><<<gblk, 256, gemm_smem>>>(xkvP, wkP, kP, 1.0f);
    gemm_h16<2><<<gblk, 256, gemm_smem>>>(xkvP, wvP, vP, 1.0f);

    const int attn_smem = 5 * KT * ASTR * (int)sizeof(__half);   // 51200
    cudaFuncSetAttribute(attn_h16, cudaFuncAttributeMaxDynamicSharedMemorySize, attn_smem);
    dim3 ga(TQ / AQ, BATCH * NHEADS);     // (32, 64)
    attn_h16<<<ga, 128, attn_smem>>>(qP, kP, vP, mP, kpm, oP, flagsP);

    gemm_h16<0><<<gblk, 256, gemm_smem>>>(oP, woP, out, 1.0f);
}

// round 12
// speedup vs baseline: 1.3256x; 1.0066x over previous
#include <cuda_runtime.h>
#include <cuda_fp16.h>
#include <math.h>

#define BATCH   4
#define TQ      2048
#define TK      2048
#define DMODEL  1024
#define NHEADS  16
#define HDIM    64
#define MROWS   (BATCH * TQ)   // 8192
#define LOG2E   1.4426950408889634f

// ---------------- scratch (__device__ globals; no allocation allowed) -------
__device__ __half h_Q[MROWS * DMODEL];   // (b,h,t,hd-interleaved), prescaled log2e/8
__device__ __half h_K[MROWS * DMODEL];   // (b,h,t,hd-interleaved)
__device__ __half h_V[MROWS * DMODEL];   // (b,h,hd,t-interleaved)  (V^T)
__device__ __half h_O[MROWS * DMODEL];   // (b,t,dmodel-interleaved)
__device__ __half h_Xq[MROWS * DMODEL];
__device__ __half h_Xkv[MROWS * DMODEL];
__device__ __half h_Wq[DMODEL * DMODEL];
__device__ __half h_Wk[DMODEL * DMODEL];
__device__ __half h_Wv[DMODEL * DMODEL];
__device__ __half h_Wo[DMODEL * DMODEL];
__device__ __half h_Mask[TQ * TK];       // additive mask, fp16
__device__ int    g_flags;               // bit0: mask nonzero, bit1: kpm nonzero

// ---------------- helpers ----------------------------------------------------
__device__ __forceinline__ void mma_f16(float* d, const unsigned* a, const unsigned* b) {
    asm volatile(
        "mma.sync.aligned.m16n8k16.row.col.f32.f16.f16.f32 "
        "{%0,%1,%2,%3}, {%4,%5,%6,%7}, {%8,%9}, {%0,%1,%2,%3};"
        : "+f"(d[0]), "+f"(d[1]), "+f"(d[2]), "+f"(d[3])
        : "r"(a[0]), "r"(a[1]), "r"(a[2]), "r"(a[3]), "r"(b[0]), "r"(b[1]));
}

__device__ __forceinline__ void cp16(void* smem_dst, const void* gmem_src) {
    unsigned s = (unsigned)__cvta_generic_to_shared(smem_dst);
    asm volatile("cp.async.cg.shared.global [%0], [%1], 16;" :: "r"(s), "l"(gmem_src));
}

__device__ __forceinline__ float ex2f(float x) {
    float r;
    asm("ex2.approx.f32 %0, %1;" : "=f"(r) : "f"(x));
    return r;
}

__device__ __forceinline__ int islot(int j) { return (j < 4) ? 2 * j : 2 * j - 7; }

// ---------------- pre-convert kernels ------------------------------------------
__device__ __forceinline__ void cvt_body(const float* __restrict__ src,
                                         __half* __restrict__ dst, int i8, float scale)
{
    float4 v0 = *(const float4*)&src[i8];
    float4 v1 = *(const float4*)&src[i8 + 4];
    int base2 = (i8 & ~15) >> 1;
    int hi = (i8 & 15) ? 1 : 0;
    __half2* d = (__half2*)dst;
    d[base2 + 0 + hi] = __floats2half2_rn(v0.x * scale, v0.y * scale);
    d[base2 + 2 + hi] = __floats2half2_rn(v0.z * scale, v0.w * scale);
    d[base2 + 4 + hi] = __floats2half2_rn(v1.x * scale, v1.y * scale);
    d[base2 + 6 + hi] = __floats2half2_rn(v1.z * scale, v1.w * scale);
}

__global__ void reset_flags_kernel(int* flags) { *flags = 0; }

__global__ void cvt_h16_kernel(const float* __restrict__ src, __half* __restrict__ dst,
                               int n, float scale)
{
    int i8 = (blockIdx.x * blockDim.x + threadIdx.x) * 8;
    if (i8 >= n) return;
    cvt_body(src, dst, i8, scale);
}

__global__ void cvt_w4_kernel(const float* w0, const float* w1,
                              const float* w2, const float* w3,
                              __half* d0, __half* d1, __half* d2, __half* d3, int n)
{
    int i8 = (blockIdx.x * blockDim.x + threadIdx.x) * 8;
    if (i8 >= n) return;
    const float* s; __half* d;
    switch (blockIdx.y) {
        case 0: s = w0; d = d0; break;
        case 1: s = w1; d = d1; break;
        case 2: s = w2; d = d2; break;
        default: s = w3; d = d3; break;
    }
    cvt_body(s, d, i8, 1.0f);
}

// mask fp32 -> fp16 + nonzero detection
__global__ void cvt_mask_kernel(const float* __restrict__ src, __half* __restrict__ dst,
                                int n, int* flags)
{
    int i8 = (blockIdx.x * blockDim.x + threadIdx.x) * 8;
    if (i8 >= n) return;
    float4 v0 = *(const float4*)&src[i8];
    float4 v1 = *(const float4*)&src[i8 + 4];
    __half2 h[4];
    h[0] = __floats2half2_rn(v0.x, v0.y);
    h[1] = __floats2half2_rn(v0.z, v0.w);
    h[2] = __floats2half2_rn(v1.x, v1.y);
    h[3] = __floats2half2_rn(v1.z, v1.w);
    *(uint4*)&dst[i8] = *(uint4*)h;
    bool nz = (v0.x != 0.f) | (v0.y != 0.f) | (v0.z != 0.f) | (v0.w != 0.f) |
              (v1.x != 0.f) | (v1.y != 0.f) | (v1.z != 0.f) | (v1.w != 0.f);
    if (__ballot_sync(0xffffffffu, nz)) {
        if ((threadIdx.x & 31) == 0) atomicOr(flags, 1);
    }
}

__global__ void kpm_check_kernel(const unsigned char* __restrict__ kpm, int n, int* flags)
{
    int i16 = (blockIdx.x * blockDim.x + threadIdx.x) * 16;
    if (i16 >= n) return;
    uint4 v = *(const uint4*)&kpm[i16];
    bool nz = (v.x | v.y | v.z | v.w) != 0u;
    if (__ballot_sync(0xffffffffu, nz)) {
        if ((threadIdx.x & 31) == 0) atomicOr(flags, 2);
    }
}

// ---------------- fp16 GEMM: C = A(M,K) @ W(N,K)^T ----------------------------
// 128x128x64 block, 128 threads, 4 warps of 64x64, cp.async double buffer.
#define BM   128
#define BN   128
#define BKH  64
#define GST  80     // halves; 40 words = 8 mod 32 -> conflict-free LDS.64

template <int MODE>
__global__ void __launch_bounds__(128, 2)
gemm_h16(const __half* __restrict__ A, const __half* __restrict__ W,
         void* __restrict__ Cv, float scale)
{
    extern __shared__ __half smh[];
    __half* As = smh;                      // [2][BM][GST]
    __half* Ws = smh + 2 * BM * GST;       // [2][BN][GST]

    const int tid  = threadIdx.x;
    const int lane = tid & 31;
    const int warp = tid >> 5;
    const int wm   = warp >> 1;            // 0..1 (64 rows)
    const int wn   = warp & 1;             // 0..1 (64 cols)
    const int bm   = blockIdx.y * BM;
    const int bn   = blockIdx.x * BN;
    const int lr   = lane >> 2;
    const int lc   = lane & 3;

    float acc[4][8][4];
#pragma unroll
    for (int i = 0; i < 4; i++)
#pragma unroll
        for (int j = 0; j < 8; j++)
#pragma unroll
            for (int c = 0; c < 4; c++) acc[i][j][c] = 0.f;

    const int NIT = DMODEL / BKH;  // 16

    auto load_stage = [&](int st, int k0) {
#pragma unroll
        for (int r = 0; r < 8; r++) {
            int id  = tid + r * 128;       // 1024 ids: 128 rows x 8 chunks
            int m   = id >> 3;
            int c8  = (id & 7) * 8;
            cp16(&As[(st * BM + m) * GST + c8], &A[(size_t)(bm + m) * DMODEL + k0 + c8]);
        }
#pragma unroll
        for (int r = 0; r < 8; r++) {
            int id  = tid + r * 128;
            int m   = id >> 3;
            int c8  = (id & 7) * 8;
            cp16(&Ws[(st * BN + m) * GST + c8], &W[(size_t)(bn + m) * DMODEL + k0 + c8]);
        }
        asm volatile("cp.async.commit_group;");
    };

    load_stage(0, 0);

    for (int it = 0; it < NIT; it++) {
        if (it + 1 < NIT) {
            load_stage((it + 1) & 1, (it + 1) * BKH);
            asm volatile("cp.async.wait_group 1;");
        } else {
            asm volatile("cp.async.wait_group 0;");
        }
        __syncthreads();
        const __half* Ab = &As[(it & 1) * BM * GST];
        const __half* Wb = &Ws[(it & 1) * BN * GST];

#pragma unroll
        for (int kk = 0; kk < 4; kk++) {
            unsigned af[4][4], bf[8][2];
#pragma unroll
            for (int mf = 0; mf < 4; mf++) {
                const int row = wm * 64 + mf * 16 + lr;
                uint2 u0 = *(const uint2*)&Ab[row * GST + kk * 16 + 4 * lc];
                uint2 u1 = *(const uint2*)&Ab[(row + 8) * GST + kk * 16 + 4 * lc];
                af[mf][0] = u0.x; af[mf][1] = u1.x; af[mf][2] = u0.y; af[mf][3] = u1.y;
            }
#pragma unroll
            for (int nf = 0; nf < 8; nf++) {
                const int row = wn * 64 + nf * 8 + lr;
                uint2 u = *(const uint2*)&Wb[row * GST + kk * 16 + 4 * lc];
                bf[nf][0] = u.x; bf[nf][1] = u.y;
            }
#pragma unroll
            for (int mf = 0; mf < 4; mf++)
#pragma unroll
                for (int nf = 0; nf < 8; nf++)
                    mma_f16(acc[mf][nf], af[mf], bf[nf]);
        }
        __syncthreads();
    }

    // epilogue
#pragma unroll
    for (int mf = 0; mf < 4; mf++) {
#pragma unroll
        for (int half = 0; half < 2; half++) {
            const int m = bm + wm * 64 + mf * 16 + lr + half * 8;
#pragma unroll
            for (int nf = 0; nf < 8; nf++) {
                const int n = bn + wn * 64 + nf * 8 + 2 * lc;
                float c0 = acc[mf][nf][half * 2], c1 = acc[mf][nf][half * 2 + 1];
                if (MODE == 0) {
                    float* C = (float*)Cv;
                    *(float2*)&C[(size_t)m * DMODEL + n] = make_float2(c0, c1);
                } else if (MODE == 1) {
                    __half* C = (__half*)Cv;
                    const int b = m >> 11, t = m & 2047;
                    const int h = n >> 6;
                    const int hd = n & 63;
                    const int offd = (hd & ~15) + 2 * islot((hd & 15) >> 1);
                    __half2 hv = __floats2half2_rn(c0 * scale, c1 * scale);
                    *(__half2*)&C[(((size_t)(b * NHEADS + h) * TQ + t) << 6) + offd] = hv;
                } else {
                    __half* C = (__half*)Cv;
                    const int b = m >> 11, t = m & 2047;
                    const int h = n >> 6;
                    const int hd0 = n & 63;
                    const int col = (t & ~15) + 2 * islot((t & 15) >> 1) + (t & 1);
                    __half* base = &C[((size_t)(b * NHEADS + h) * HDIM) * (size_t)TK];
                    base[(size_t)hd0 * TK + col]       = __float2half_rn(c0);
                    base[(size_t)(hd0 + 1) * TK + col] = __float2half_rn(c1);
                }
            }
        }
    }
}

// ---------------- fused attention, fp16 mma, log2-domain softmax ----------------
// 64 q-rows, 4 warps (16 rows each); KT=64 keys; K+V double-buffered, one
// wait+sync per tile. Q prescaled by log2e/8 -> softmax via exp2 (h2exp2).
#define AQ   64
#define KT   64
#define ASTR 80

__global__ void __launch_bounds__(128, 3)
attn_h16(const __half* __restrict__ Q, const __half* __restrict__ K,
         const __half* __restrict__ V, const __half* __restrict__ mask,
         const unsigned char* __restrict__ kpm, __half* __restrict__ O,
         const int* __restrict__ flagsP)
{
    extern __shared__ __half smh[];
    __half* Qs = smh;                      // 64 x 80
    __half* Ks = smh + AQ * ASTR;          // [2][64][80]
    __half* Vs = Ks + 2 * KT * ASTR;       // [2][64][80] (V^T)

    const int tid  = threadIdx.x;
    const int lane = tid & 31;
    const int warp = tid >> 5;
    const int lr   = lane >> 2;
    const int lc   = lane & 3;

    const int q0 = blockIdx.x * AQ;
    const int bh = blockIdx.y;
    const int b  = bh >> 4;
    const int h  = bh & 15;

    const bool plain = (*flagsP == 0);

    const __half* Qb = Q + (size_t)bh * TQ * HDIM;
    const __half* Kb = K + (size_t)bh * TK * HDIM;
    const __half* Vb = V + (size_t)bh * HDIM * TK;

#pragma unroll
    for (int r = 0; r < 4; r++) {
        int id = tid + r * 128;
        int row = id >> 3, c8 = (id & 7) * 8;
        cp16(&Qs[row * ASTR + c8], &Qb[(size_t)(q0 + row) * HDIM + c8]);
    }
    asm volatile("cp.async.commit_group;");

    auto cp_KV = [&](int st, int kt) {
        const int k0 = kt * KT;
#pragma unroll
        for (int r = 0; r < 4; r++) {
            int id = tid + r * 128;
            int row = id >> 3, c8 = (id & 7) * 8;
            cp16(&Ks[st * KT * ASTR + row * ASTR + c8], &Kb[(size_t)(k0 + row) * HDIM + c8]);
        }
#pragma unroll
        for (int r = 0; r < 4; r++) {
            int id = tid + r * 128;
            int row = id >> 3, c8 = (id & 7) * 8;   // row = hd
            cp16(&Vs[st * KT * ASTR + row * ASTR + c8], &Vb[(size_t)row * TK + k0 + c8]);
        }
        asm volatile("cp.async.commit_group;");
    };

    cp_KV(0, 0);

    asm volatile("cp.async.wait_group 1;");
    __syncthreads();

    unsigned qf[4][4];
#pragma unroll
    for (int kk = 0; kk < 4; kk++) {
        const int row = warp * 16 + lr;
        uint2 u0 = *(const uint2*)&Qs[row * ASTR + kk * 16 + 4 * lc];
        uint2 u1 = *(const uint2*)&Qs[(row + 8) * ASTR + kk * 16 + 4 * lc];
        qf[kk][0] = u0.x; qf[kk][1] = u1.x; qf[kk][2] = u0.y; qf[kk][3] = u1.y;
    }

    float m_i[2] = {-INFINITY, -INFINITY};
    float l_i[2] = {0.f, 0.f};
    float o[8][4];
#pragma unroll
    for (int nf = 0; nf < 8; nf++)
#pragma unroll
        for (int c = 0; c < 4; c++) o[nf][c] = 0.f;

    const int NT = TK / KT;   // 32
    for (int kt = 0; kt < NT; kt++) {
        const int k0 = kt * KT;

        asm volatile("cp.async.wait_group 0;");
        __syncthreads();

        if (kt + 1 < NT) cp_KV((kt + 1) & 1, kt + 1);

        const __half* Kst = &Ks[(kt & 1) * KT * ASTR];
        const __half* Vst = &Vs[(kt & 1) * KT * ASTR];

        // S = Q @ K^T  (log2 domain: Q prescaled by log2e/8)
        float s[8][4];
#pragma unroll
        for (int nf = 0; nf < 8; nf++)
#pragma unroll
            for (int c = 0; c < 4; c++) s[nf][c] = 0.f;

#pragma unroll
        for (int kk = 0; kk < 4; kk++) {
#pragma unroll
            for (int nf = 0; nf < 8; nf++) {
                unsigned bf[2];
                uint2 u = *(const uint2*)&Kst[(nf * 8 + lr) * ASTR + kk * 16 + 4 * lc];
                bf[0] = u.x; bf[1] = u.y;
                mma_f16(s[nf], qf[kk], bf);
            }
        }

        // masked variant: apply mask (scaled to log2 domain) + kpm before softmax
        if (!plain) {
            uchar2 kp[8];
#pragma unroll
            for (int nf = 0; nf < 8; nf++)
                kp[nf] = *(const uchar2*)&kpm[(size_t)b * TK + k0 + nf * 8 + 2 * lc];
#pragma unroll
            for (int hf = 0; hf < 2; hf++) {
                const int qg = q0 + warp * 16 + lr + hf * 8;
                const __half* mrow = &mask[(size_t)qg * TK + k0];
#pragma unroll
                for (int nf = 0; nf < 8; nf++) {
                    float2 mv = __half22float2(*(const __half2*)&mrow[nf * 8 + 2 * lc]);
                    float v0 = s[nf][hf * 2]     + mv.x * LOG2E;
                    float v1 = s[nf][hf * 2 + 1] + mv.y * LOG2E;
                    if (kp[nf].x) v0 = -INFINITY;
                    if (kp[nf].y) v1 = -INFINITY;
                    s[nf][hf * 2]     = v0;
                    s[nf][hf * 2 + 1] = v1;
                }
            }
        }

        // online softmax (log2 domain) -> packed fp16 P fragments
        unsigned e[8][2];
#pragma unroll
        for (int hf = 0; hf < 2; hf++) {
            float mx = -INFINITY;
#pragma unroll
            for (int nf = 0; nf < 8; nf++)
                mx = fmaxf(mx, fmaxf(s[nf][hf * 2], s[nf][hf * 2 + 1]));
            mx = fmaxf(mx, __shfl_xor_sync(0xffffffffu, mx, 1));
            mx = fmaxf(mx, __shfl_xor_sync(0xffffffffu, mx, 2));
            float mnew = fmaxf(m_i[hf], mx);
            float alpha, rs = 0.f;
            if (mnew == -INFINITY) {          // fully masked so far (slow path only)
                alpha = 1.f;
#pragma unroll
                for (int nf = 0; nf < 8; nf++) e[nf][hf] = 0u;
            } else {
                alpha = ex2f(m_i[hf] - mnew); // 0 when m_i == -inf
#pragma unroll
                for (int nf = 0; nf < 8; nf++) {
                    __half2 xh = __floats2half2_rn(s[nf][hf * 2] - mnew,
                                                   s[nf][hf * 2 + 1] - mnew);
                    __half2 ph = h2exp2(xh);
                    e[nf][hf] = *(unsigned*)&ph;
                    float2 pf = __half22float2(ph);
                    rs += pf.x + pf.y;
                }
            }
            rs += __shfl_xor_sync(0xffffffffu, rs, 1);
            rs += __shfl_xor_sync(0xffffffffu, rs, 2);
            l_i[hf] = l_i[hf] * alpha + rs;
            m_i[hf] = mnew;
#pragma unroll
            for (int nf = 0; nf < 8; nf++) {
                o[nf][hf * 2]     *= alpha;
                o[nf][hf * 2 + 1] *= alpha;
            }
        }

        // O += P @ V  (A-fragments are the packed exp2 results)
#pragma unroll
        for (int kb = 0; kb < 4; kb++) {
            unsigned af[4];
            af[0] = e[2 * kb][0];
            af[1] = e[2 * kb][1];
            af[2] = e[2 * kb + 1][0];
            af[3] = e[2 * kb + 1][1];
#pragma unroll
            for (int nf = 0; nf < 8; nf++) {
                unsigned bf[2];
                uint2 u = *(const uint2*)&Vst[(nf * 8 + lr) * ASTR + kb * 16 + 4 * lc];
                bf[0] = u.x; bf[1] = u.y;
                mma_f16(o[nf], af, bf);
            }
        }
    }

    // finalize: (b,t,dmodel-interleaved) fp16
#pragma unroll
    for (int hf = 0; hf < 2; hf++) {
        const float inv = (l_i[hf] > 0.f) ? (1.f / l_i[hf]) : 0.f;
        const int t = q0 + warp * 16 + lr + hf * 8;
#pragma unroll
        for (int nf = 0; nf < 8; nf++) {
            const int n = h * HDIM + nf * 8 + 2 * lc;
            const int offd = (n & ~15) + 2 * islot((n & 15) >> 1);
            __half2 hv = __floats2half2_rn(o[nf][hf * 2] * inv, o[nf][hf * 2 + 1] * inv);
            *(__half2*)&O[((size_t)(b * TQ + t)) * DMODEL + offd] = hv;
        }
    }
}

// ---------------- launch --------------------------------------------------------
extern "C" void kernel_launch(void* const* d_in, const int* in_sizes, int n_in,
                              void* d_out, int out_size)
{
    const float* x_q   = (const float*)d_in[0];
    const float* x_kv  = (const float*)d_in[1];
    const float* amask = (const float*)d_in[2];
    const unsigned char* kpm = (const unsigned char*)d_in[3];
    const float* Wq = (const float*)d_in[4];
    const float* Wk = (const float*)d_in[5];
    const float* Wv = (const float*)d_in[6];
    const float* Wo = (const float*)d_in[7];
    float* out = (float*)d_out;

    __half *qP, *kP, *vP, *oP, *xqP, *xkvP, *wqP, *wkP, *wvP, *woP, *mP;
    int* flagsP;
    cudaGetSymbolAddress((void**)&qP,  h_Q);
    cudaGetSymbolAddress((void**)&kP,  h_K);
    cudaGetSymbolAddress((void**)&vP,  h_V);
    cudaGetSymbolAddress((void**)&oP,  h_O);
    cudaGetSymbolAddress((void**)&xqP, h_Xq);
    cudaGetSymbolAddress((void**)&xkvP,h_Xkv);
    cudaGetSymbolAddress((void**)&wqP, h_Wq);
    cudaGetSymbolAddress((void**)&wkP, h_Wk);
    cudaGetSymbolAddress((void**)&wvP, h_Wv);
    cudaGetSymbolAddress((void**)&woP, h_Wo);
    cudaGetSymbolAddress((void**)&mP,  h_Mask);
    cudaGetSymbolAddress((void**)&flagsP, g_flags);

    const int NX = MROWS * DMODEL;   // 8M
    const int NW = DMODEL * DMODEL;  // 1M
    const int NM = TQ * TK;          // 4M
    reset_flags_kernel<<<1, 1>>>(flagsP);
    cvt_h16_kernel<<<NX / 8 / 256, 256>>>(x_q,  xqP,  NX, 1.0f);
    cvt_h16_kernel<<<NX / 8 / 256, 256>>>(x_kv, xkvP, NX, 1.0f);
    dim3 gw(NW / 8 / 256, 4);
    cvt_w4_kernel<<<gw, 256>>>(Wq, Wk, Wv, Wo, wqP, wkP, wvP, woP, NW);
    cvt_mask_kernel<<<NM / 8 / 256, 256>>>(amask, mP, NM, flagsP);
    kpm_check_kernel<<<(BATCH * TK) / 16 / 256 + 1, 256>>>(kpm, BATCH * TK, flagsP);

    const int gemm_smem = 2 * (BM + BN) * GST * (int)sizeof(__half);   // 81920
    cudaFuncSetAttribute(gemm_h16<0>, cudaFuncAttributeMaxDynamicSharedMemorySize, gemm_smem);
    cudaFuncSetAttribute(gemm_h16<1>, cudaFuncAttributeMaxDynamicSharedMemorySize, gemm_smem);
    cudaFuncSetAttribute(gemm_h16<2>, cudaFuncAttributeMaxDynamicSharedMemorySize, gemm_smem);

    // Q prescale folds softmax 1/sqrt(hd) AND log2e (softmax done in log2 domain)
    const float qscale = 0.125f * LOG2E;

    dim3 gblk(DMODEL / BN, MROWS / BM);   // (8, 64)
    gemm_h16<1><<<gblk, 128, gemm_smem>>>(xqP,  wqP, qP, qscale);
    gemm_h16<1><<<gblk, 128, gemm_smem>>>(xkvP, wkP, kP, 1.0f);
    gemm_h16<2><<<gblk, 128, gemm_smem>>>(xkvP, wvP, vP, 1.0f);

    const int attn_smem = 5 * KT * ASTR * (int)sizeof(__half);   // 51200
    cudaFuncSetAttribute(attn_h16, cudaFuncAttributeMaxDynamicSharedMemorySize, attn_smem);
    dim3 ga(TQ / AQ, BATCH * NHEADS);     // (32, 64)
    attn_h16<<<ga, 128, attn_smem>>>(qP, kP, vP, mP, kpm, oP, flagsP);

    gemm_h16<0><<<gblk, 128, gemm_smem>>>(oP, woP, out, 1.0f);
}

// round 13
// speedup vs baseline: 1.3578x; 1.0243x over previous
#include <cuda_runtime.h>
#include <cuda_fp16.h>
#include <math.h>

#define BATCH   4
#define TQ      2048
#define TK      2048
#define DMODEL  1024
#define NHEADS  16
#define HDIM    64
#define MROWS   (BATCH * TQ)   // 8192
#define LOG2E   1.4426950408889634f

// ---------------- scratch (__device__ globals; no allocation allowed) -------
__device__ __half h_Q[MROWS * DMODEL];   // (b,h,t,hd-interleaved), prescaled log2e/8
__device__ __half h_K[MROWS * DMODEL];   // (b,h,t,hd-interleaved)
__device__ __half h_V[MROWS * DMODEL];   // (b,h,hd,t-interleaved)  (V^T)
__device__ __half h_O[MROWS * DMODEL];   // (b,t,dmodel-interleaved)
__device__ __half h_Xq[MROWS * DMODEL];
__device__ __half h_Xkv[MROWS * DMODEL];
__device__ __half h_Wq[DMODEL * DMODEL];
__device__ __half h_Wk[DMODEL * DMODEL];
__device__ __half h_Wv[DMODEL * DMODEL];
__device__ __half h_Wo[DMODEL * DMODEL];
__device__ __half h_Mask[TQ * TK];       // additive mask, fp16
__device__ int    g_flags;               // bit0: mask nonzero, bit1: kpm nonzero

// ---------------- helpers ----------------------------------------------------
__device__ __forceinline__ void mma_f16(float* d, const unsigned* a, const unsigned* b) {
    asm volatile(
        "mma.sync.aligned.m16n8k16.row.col.f32.f16.f16.f32 "
        "{%0,%1,%2,%3}, {%4,%5,%6,%7}, {%8,%9}, {%0,%1,%2,%3};"
        : "+f"(d[0]), "+f"(d[1]), "+f"(d[2]), "+f"(d[3])
        : "r"(a[0]), "r"(a[1]), "r"(a[2]), "r"(a[3]), "r"(b[0]), "r"(b[1]));
}

__device__ __forceinline__ void cp16(void* smem_dst, const void* gmem_src) {
    unsigned s = (unsigned)__cvta_generic_to_shared(smem_dst);
    asm volatile("cp.async.cg.shared.global [%0], [%1], 16;" :: "r"(s), "l"(gmem_src));
}

__device__ __forceinline__ float ex2f(float x) {
    float r;
    asm("ex2.approx.f32 %0, %1;" : "=f"(r) : "f"(x));
    return r;
}

__device__ __forceinline__ int islot(int j) { return (j < 4) ? 2 * j : 2 * j - 7; }

// ---------------- pre-convert kernels ------------------------------------------
__device__ __forceinline__ void cvt_body(const float* __restrict__ src,
                                         __half* __restrict__ dst, int i8, float scale)
{
    float4 v0 = *(const float4*)&src[i8];
    float4 v1 = *(const float4*)&src[i8 + 4];
    int base2 = (i8 & ~15) >> 1;
    int hi = (i8 & 15) ? 1 : 0;
    __half2* d = (__half2*)dst;
    d[base2 + 0 + hi] = __floats2half2_rn(v0.x * scale, v0.y * scale);
    d[base2 + 2 + hi] = __floats2half2_rn(v0.z * scale, v0.w * scale);
    d[base2 + 4 + hi] = __floats2half2_rn(v1.x * scale, v1.y * scale);
    d[base2 + 6 + hi] = __floats2half2_rn(v1.z * scale, v1.w * scale);
}

__global__ void reset_flags_kernel(int* flags) { *flags = 0; }

// fused x_q / x_kv conversion (grid.y selects)
__global__ void cvt_x2_kernel(const float* x0, const float* x1,
                              __half* d0, __half* d1, int n)
{
    int i8 = (blockIdx.x * blockDim.x + threadIdx.x) * 8;
    if (i8 >= n) return;
    if (blockIdx.y == 0) cvt_body(x0, d0, i8, 1.0f);
    else                 cvt_body(x1, d1, i8, 1.0f);
}

__global__ void cvt_w4_kernel(const float* w0, const float* w1,
                              const float* w2, const float* w3,
                              __half* d0, __half* d1, __half* d2, __half* d3, int n)
{
    int i8 = (blockIdx.x * blockDim.x + threadIdx.x) * 8;
    if (i8 >= n) return;
    const float* s; __half* d;
    switch (blockIdx.y) {
        case 0: s = w0; d = d0; break;
        case 1: s = w1; d = d1; break;
        case 2: s = w2; d = d2; break;
        default: s = w3; d = d3; break;
    }
    cvt_body(s, d, i8, 1.0f);
}

// mask fp32 -> fp16 + nonzero detection
__global__ void cvt_mask_kernel(const float* __restrict__ src, __half* __restrict__ dst,
                                int n, int* flags)
{
    int i8 = (blockIdx.x * blockDim.x + threadIdx.x) * 8;
    if (i8 >= n) return;
    float4 v0 = *(const float4*)&src[i8];
    float4 v1 = *(const float4*)&src[i8 + 4];
    __half2 h[4];
    h[0] = __floats2half2_rn(v0.x, v0.y);
    h[1] = __floats2half2_rn(v0.z, v0.w);
    h[2] = __floats2half2_rn(v1.x, v1.y);
    h[3] = __floats2half2_rn(v1.z, v1.w);
    *(uint4*)&dst[i8] = *(uint4*)h;
    bool nz = (v0.x != 0.f) | (v0.y != 0.f) | (v0.z != 0.f) | (v0.w != 0.f) |
              (v1.x != 0.f) | (v1.y != 0.f) | (v1.z != 0.f) | (v1.w != 0.f);
    if (__ballot_sync(0xffffffffu, nz)) {
        if ((threadIdx.x & 31) == 0) atomicOr(flags, 1);
    }
}

__global__ void kpm_check_kernel(const unsigned char* __restrict__ kpm, int n, int* flags)
{
    int i16 = (blockIdx.x * blockDim.x + threadIdx.x) * 16;
    if (i16 >= n) return;
    uint4 v = *(const uint4*)&kpm[i16];
    bool nz = (v.x | v.y | v.z | v.w) != 0u;
    if (__ballot_sync(0xffffffffu, nz)) {
        if ((threadIdx.x & 31) == 0) atomicOr(flags, 2);
    }
}

// ---------------- fp16 GEMM core: 128x128x64, 256 thr, 8 warps of 64x32 --------
#define BM   128
#define BN   128
#define BKH  64
#define GST  80     // halves; 40 words = 8 mod 32 -> conflict-free LDS.64

// Shared mainloop; epilogue mode: 0 = fp32 row-major, 1 = split-heads interleaved
// fp16 (*scale), 2 = V^T (b,h,hd,t-interleaved) fp16.
__device__ __forceinline__ void gemm_core(
    const __half* __restrict__ A, const __half* __restrict__ W,
    void* __restrict__ Cv, float scale, int mode, int bm, int bn)
{
    extern __shared__ __half smh[];
    __half* As = smh;                      // [2][BM][GST]
    __half* Ws = smh + 2 * BM * GST;       // [2][BN][GST]

    const int tid  = threadIdx.x;
    const int lane = tid & 31;
    const int warp = tid >> 5;
    const int wm   = warp >> 2;
    const int wn   = warp & 3;
    const int lr   = lane >> 2;
    const int lc   = lane & 3;

    float acc[4][4][4];
#pragma unroll
    for (int i = 0; i < 4; i++)
#pragma unroll
        for (int j = 0; j < 4; j++)
#pragma unroll
            for (int c = 0; c < 4; c++) acc[i][j][c] = 0.f;

    const int NIT = DMODEL / BKH;  // 16

    auto load_stage = [&](int st, int k0) {
#pragma unroll
        for (int r = 0; r < 4; r++) {
            int id  = tid + r * 256;
            int m   = id >> 3;
            int c8  = (id & 7) * 8;
            cp16(&As[(st * BM + m) * GST + c8], &A[(size_t)(bm + m) * DMODEL + k0 + c8]);
        }
#pragma unroll
        for (int r = 0; r < 4; r++) {
            int id  = tid + r * 256;
            int m   = id >> 3;
            int c8  = (id & 7) * 8;
            cp16(&Ws[(st * BN + m) * GST + c8], &W[(size_t)(bn + m) * DMODEL + k0 + c8]);
        }
        asm volatile("cp.async.commit_group;");
    };

    load_stage(0, 0);

    for (int it = 0; it < NIT; it++) {
        if (it + 1 < NIT) {
            load_stage((it + 1) & 1, (it + 1) * BKH);
            asm volatile("cp.async.wait_group 1;");
        } else {
            asm volatile("cp.async.wait_group 0;");
        }
        __syncthreads();
        const __half* Ab = &As[(it & 1) * BM * GST];
        const __half* Wb = &Ws[(it & 1) * BN * GST];

#pragma unroll
        for (int kk = 0; kk < 4; kk++) {
            unsigned af[4][4], bf[4][2];
#pragma unroll
            for (int mf = 0; mf < 4; mf++) {
                const int row = wm * 64 + mf * 16 + lr;
                uint2 u0 = *(const uint2*)&Ab[row * GST + kk * 16 + 4 * lc];
                uint2 u1 = *(const uint2*)&Ab[(row + 8) * GST + kk * 16 + 4 * lc];
                af[mf][0] = u0.x; af[mf][1] = u1.x; af[mf][2] = u0.y; af[mf][3] = u1.y;
            }
#pragma unroll
            for (int nf = 0; nf < 4; nf++) {
                const int row = wn * 32 + nf * 8 + lr;
                uint2 u = *(const uint2*)&Wb[row * GST + kk * 16 + 4 * lc];
                bf[nf][0] = u.x; bf[nf][1] = u.y;
            }
#pragma unroll
            for (int mf = 0; mf < 4; mf++)
#pragma unroll
                for (int nf = 0; nf < 4; nf++)
                    mma_f16(acc[mf][nf], af[mf], bf[nf]);
        }
        __syncthreads();
    }

    // epilogue
#pragma unroll
    for (int mf = 0; mf < 4; mf++) {
#pragma unroll
        for (int half = 0; half < 2; half++) {
            const int m = bm + wm * 64 + mf * 16 + lr + half * 8;
#pragma unroll
            for (int nf = 0; nf < 4; nf++) {
                const int n = bn + wn * 32 + nf * 8 + 2 * lc;
                float c0 = acc[mf][nf][half * 2], c1 = acc[mf][nf][half * 2 + 1];
                if (mode == 0) {
                    float* C = (float*)Cv;
                    *(float2*)&C[(size_t)m * DMODEL + n] = make_float2(c0, c1);
                } else if (mode == 1) {
                    __half* C = (__half*)Cv;
                    const int b = m >> 11, t = m & 2047;
                    const int h = n >> 6;
                    const int hd = n & 63;
                    const int offd = (hd & ~15) + 2 * islot((hd & 15) >> 1);
                    __half2 hv = __floats2half2_rn(c0 * scale, c1 * scale);
                    *(__half2*)&C[(((size_t)(b * NHEADS + h) * TQ + t) << 6) + offd] = hv;
                } else {
                    __half* C = (__half*)Cv;
                    const int b = m >> 11, t = m & 2047;
                    const int h = n >> 6;
                    const int hd0 = n & 63;
                    const int col = (t & ~15) + 2 * islot((t & 15) >> 1) + (t & 1);
                    __half* base = &C[((size_t)(b * NHEADS + h) * HDIM) * (size_t)TK];
                    base[(size_t)hd0 * TK + col]       = __float2half_rn(c0);
                    base[(size_t)(hd0 + 1) * TK + col] = __float2half_rn(c1);
                }
            }
        }
    }
}

// fused Q/K/V projections: grid.z selects operand set + epilogue mode
__global__ void __launch_bounds__(256, 2)
gemm_qkv(const __half* __restrict__ xq, const __half* __restrict__ xkv,
         const __half* __restrict__ wq, const __half* __restrict__ wk,
         const __half* __restrict__ wv,
         __half* __restrict__ qP, __half* __restrict__ kP, __half* __restrict__ vP,
         float qscale)
{
    const int bm = blockIdx.y * BM;
    const int bn = blockIdx.x * BN;
    if (blockIdx.z == 0)      gemm_core(xq,  wq, qP, qscale, 1, bm, bn);
    else if (blockIdx.z == 1) gemm_core(xkv, wk, kP, 1.0f,   1, bm, bn);
    else                      gemm_core(xkv, wv, vP, 1.0f,   2, bm, bn);
}

// final output projection (fp32 out)
__global__ void __launch_bounds__(256, 2)
gemm_out(const __half* __restrict__ A, const __half* __restrict__ W,
         float* __restrict__ C)
{
    gemm_core(A, W, C, 1.0f, 0, blockIdx.y * BM, blockIdx.x * BN);
}

// ---------------- fused attention, fp16 mma, log2-domain softmax ----------------
#define AQ   64
#define KT   64
#define ASTR 80

__global__ void __launch_bounds__(128, 3)
attn_h16(const __half* __restrict__ Q, const __half* __restrict__ K,
         const __half* __restrict__ V, const __half* __restrict__ mask,
         const unsigned char* __restrict__ kpm, __half* __restrict__ O,
         const int* __restrict__ flagsP)
{
    extern __shared__ __half smh[];
    __half* Qs = smh;                      // 64 x 80
    __half* Ks = smh + AQ * ASTR;          // [2][64][80]
    __half* Vs = Ks + 2 * KT * ASTR;       // [2][64][80] (V^T)

    const int tid  = threadIdx.x;
    const int lane = tid & 31;
    const int warp = tid >> 5;
    const int lr   = lane >> 2;
    const int lc   = lane & 3;

    const int q0 = blockIdx.x * AQ;
    const int bh = blockIdx.y;
    const int b  = bh >> 4;
    const int h  = bh & 15;

    const bool plain = (*flagsP == 0);

    const __half* Qb = Q + (size_t)bh * TQ * HDIM;
    const __half* Kb = K + (size_t)bh * TK * HDIM;
    const __half* Vb = V + (size_t)bh * HDIM * TK;

#pragma unroll
    for (int r = 0; r < 4; r++) {
        int id = tid + r * 128;
        int row = id >> 3, c8 = (id & 7) * 8;
        cp16(&Qs[row * ASTR + c8], &Qb[(size_t)(q0 + row) * HDIM + c8]);
    }
    asm volatile("cp.async.commit_group;");

    auto cp_KV = [&](int st, int kt) {
        const int k0 = kt * KT;
#pragma unroll
        for (int r = 0; r < 4; r++) {
            int id = tid + r * 128;
            int row = id >> 3, c8 = (id & 7) * 8;
            cp16(&Ks[st * KT * ASTR + row * ASTR + c8], &Kb[(size_t)(k0 + row) * HDIM + c8]);
        }
#pragma unroll
        for (int r = 0; r < 4; r++) {
            int id = tid + r * 128;
            int row = id >> 3, c8 = (id & 7) * 8;   // row = hd
            cp16(&Vs[st * KT * ASTR + row * ASTR + c8], &Vb[(size_t)row * TK + k0 + c8]);
        }
        asm volatile("cp.async.commit_group;");
    };

    cp_KV(0, 0);

    asm volatile("cp.async.wait_group 1;");
    __syncthreads();

    unsigned qf[4][4];
#pragma unroll
    for (int kk = 0; kk < 4; kk++) {
        const int row = warp * 16 + lr;
        uint2 u0 = *(const uint2*)&Qs[row * ASTR + kk * 16 + 4 * lc];
        uint2 u1 = *(const uint2*)&Qs[(row + 8) * ASTR + kk * 16 + 4 * lc];
        qf[kk][0] = u0.x; qf[kk][1] = u1.x; qf[kk][2] = u0.y; qf[kk][3] = u1.y;
    }

    float m_i[2] = {-INFINITY, -INFINITY};
    float l_i[2] = {0.f, 0.f};
    float o[8][4];
#pragma unroll
    for (int nf = 0; nf < 8; nf++)
#pragma unroll
        for (int c = 0; c < 4; c++) o[nf][c] = 0.f;

    const int NT = TK / KT;   // 32
    for (int kt = 0; kt < NT; kt++) {
        const int k0 = kt * KT;

        asm volatile("cp.async.wait_group 0;");
        __syncthreads();

        if (kt + 1 < NT) cp_KV((kt + 1) & 1, kt + 1);

        const __half* Kst = &Ks[(kt & 1) * KT * ASTR];
        const __half* Vst = &Vs[(kt & 1) * KT * ASTR];

        // S = Q @ K^T  (log2 domain)
        float s[8][4];
#pragma unroll
        for (int nf = 0; nf < 8; nf++)
#pragma unroll
            for (int c = 0; c < 4; c++) s[nf][c] = 0.f;

#pragma unroll
        for (int kk = 0; kk < 4; kk++) {
#pragma unroll
            for (int nf = 0; nf < 8; nf++) {
                unsigned bf[2];
                uint2 u = *(const uint2*)&Kst[(nf * 8 + lr) * ASTR + kk * 16 + 4 * lc];
                bf[0] = u.x; bf[1] = u.y;
                mma_f16(s[nf], qf[kk], bf);
            }
        }

        if (!plain) {
            uchar2 kp[8];
#pragma unroll
            for (int nf = 0; nf < 8; nf++)
                kp[nf] = *(const uchar2*)&kpm[(size_t)b * TK + k0 + nf * 8 + 2 * lc];
#pragma unroll
            for (int hf = 0; hf < 2; hf++) {
                const int qg = q0 + warp * 16 + lr + hf * 8;
                const __half* mrow = &mask[(size_t)qg * TK + k0];
#pragma unroll
                for (int nf = 0; nf < 8; nf++) {
                    float2 mv = __half22float2(*(const __half2*)&mrow[nf * 8 + 2 * lc]);
                    float v0 = s[nf][hf * 2]     + mv.x * LOG2E;
                    float v1 = s[nf][hf * 2 + 1] + mv.y * LOG2E;
                    if (kp[nf].x) v0 = -INFINITY;
                    if (kp[nf].y) v1 = -INFINITY;
                    s[nf][hf * 2]     = v0;
                    s[nf][hf * 2 + 1] = v1;
                }
            }
        }

        // online softmax (log2 domain) -> packed fp16 P fragments
        unsigned e[8][2];
#pragma unroll
        for (int hf = 0; hf < 2; hf++) {
            float mx = -INFINITY;
#pragma unroll
            for (int nf = 0; nf < 8; nf++)
                mx = fmaxf(mx, fmaxf(s[nf][hf * 2], s[nf][hf * 2 + 1]));
            mx = fmaxf(mx, __shfl_xor_sync(0xffffffffu, mx, 1));
            mx = fmaxf(mx, __shfl_xor_sync(0xffffffffu, mx, 2));
            float mnew = fmaxf(m_i[hf], mx);
            float alpha, rs = 0.f;
            if (mnew == -INFINITY) {
                alpha = 1.f;
#pragma unroll
                for (int nf = 0; nf < 8; nf++) e[nf][hf] = 0u;
            } else {
                alpha = ex2f(m_i[hf] - mnew);
#pragma unroll
                for (int nf = 0; nf < 8; nf++) {
                    __half2 xh = __floats2half2_rn(s[nf][hf * 2] - mnew,
                                                   s[nf][hf * 2 + 1] - mnew);
                    __half2 ph = h2exp2(xh);
                    e[nf][hf] = *(unsigned*)&ph;
                    float2 pf = __half22float2(ph);
                    rs += pf.x + pf.y;
                }
            }
            rs += __shfl_xor_sync(0xffffffffu, rs, 1);
            rs += __shfl_xor_sync(0xffffffffu, rs, 2);
            l_i[hf] = l_i[hf] * alpha + rs;
            m_i[hf] = mnew;
#pragma unroll
            for (int nf = 0; nf < 8; nf++) {
                o[nf][hf * 2]     *= alpha;
                o[nf][hf * 2 + 1] *= alpha;
            }
        }

        // O += P @ V
#pragma unroll
        for (int kb = 0; kb < 4; kb++) {
            unsigned af[4];
            af[0] = e[2 * kb][0];
            af[1] = e[2 * kb][1];
            af[2] = e[2 * kb + 1][0];
            af[3] = e[2 * kb + 1][1];
#pragma unroll
            for (int nf = 0; nf < 8; nf++) {
                unsigned bf[2];
                uint2 u = *(const uint2*)&Vst[(nf * 8 + lr) * ASTR + kb * 16 + 4 * lc];
                bf[0] = u.x; bf[1] = u.y;
                mma_f16(o[nf], af, bf);
            }
        }
    }

    // finalize: (b,t,dmodel-interleaved) fp16
#pragma unroll
    for (int hf = 0; hf < 2; hf++) {
        const float inv = (l_i[hf] > 0.f) ? (1.f / l_i[hf]) : 0.f;
        const int t = q0 + warp * 16 + lr + hf * 8;
#pragma unroll
        for (int nf = 0; nf < 8; nf++) {
            const int n = h * HDIM + nf * 8 + 2 * lc;
            const int offd = (n & ~15) + 2 * islot((n & 15) >> 1);
            __half2 hv = __floats2half2_rn(o[nf][hf * 2] * inv, o[nf][hf * 2 + 1] * inv);
            *(__half2*)&O[((size_t)(b * TQ + t)) * DMODEL + offd] = hv;
        }
    }
}

// ---------------- launch --------------------------------------------------------
extern "C" void kernel_launch(void* const* d_in, const int* in_sizes, int n_in,
                              void* d_out, int out_size)
{
    const float* x_q   = (const float*)d_in[0];
    const float* x_kv  = (const float*)d_in[1];
    const float* amask = (const float*)d_in[2];
    const unsigned char* kpm = (const unsigned char*)d_in[3];
    const float* Wq = (const float*)d_in[4];
    const float* Wk = (const float*)d_in[5];
    const float* Wv = (const float*)d_in[6];
    const float* Wo = (const float*)d_in[7];
    float* out = (float*)d_out;

    __half *qP, *kP, *vP, *oP, *xqP, *xkvP, *wqP, *wkP, *wvP, *woP, *mP;
    int* flagsP;
    cudaGetSymbolAddress((void**)&qP,  h_Q);
    cudaGetSymbolAddress((void**)&kP,  h_K);
    cudaGetSymbolAddress((void**)&vP,  h_V);
    cudaGetSymbolAddress((void**)&oP,  h_O);
    cudaGetSymbolAddress((void**)&xqP, h_Xq);
    cudaGetSymbolAddress((void**)&xkvP,h_Xkv);
    cudaGetSymbolAddress((void**)&wqP, h_Wq);
    cudaGetSymbolAddress((void**)&wkP, h_Wk);
    cudaGetSymbolAddress((void**)&wvP, h_Wv);
    cudaGetSymbolAddress((void**)&woP, h_Wo);
    cudaGetSymbolAddress((void**)&mP,  h_Mask);
    cudaGetSymbolAddress((void**)&flagsP, g_flags);

    const int NX = MROWS * DMODEL;   // 8M
    const int NW = DMODEL * DMODEL;  // 1M
    const int NM = TQ * TK;          // 4M
    reset_flags_kernel<<<1, 1>>>(flagsP);
    dim3 gx(NX / 8 / 256, 2);
    cvt_x2_kernel<<<gx, 256>>>(x_q, x_kv, xqP, xkvP, NX);
    dim3 gw(NW / 8 / 256, 4);
    cvt_w4_kernel<<<gw, 256>>>(Wq, Wk, Wv, Wo, wqP, wkP, wvP, woP, NW);
    cvt_mask_kernel<<<NM / 8 / 256, 256>>>(amask, mP, NM, flagsP);
    kpm_check_kernel<<<(BATCH * TK) / 16 / 256 + 1, 256>>>(kpm, BATCH * TK, flagsP);

    const int gemm_smem = 2 * (BM + BN) * GST * (int)sizeof(__half);   // 81920
    cudaFuncSetAttribute(gemm_qkv, cudaFuncAttributeMaxDynamicSharedMemorySize, gemm_smem);
    cudaFuncSetAttribute(gemm_out, cudaFuncAttributeMaxDynamicSharedMemorySize, gemm_smem);

    const float qscale = 0.125f * LOG2E;

    dim3 gqkv(DMODEL / BN, MROWS / BM, 3);   // (8, 64, 3)
    gemm_qkv<<<gqkv, 256, gemm_smem>>>(xqP, xkvP, wqP, wkP, wvP, qP, kP, vP, qscale);

    const int attn_smem = 5 * KT * ASTR * (int)sizeof(__half);   // 51200
    cudaFuncSetAttribute(attn_h16, cudaFuncAttributeMaxDynamicSharedMemorySize, attn_smem);
    dim3 ga(TQ / AQ, BATCH * NHEADS);     // (32, 64)
    attn_h16<<<ga, 128, attn_smem>>>(qP, kP, vP, mP, kpm, oP, flagsP);

    dim3 gout(DMODEL / BN, MROWS / BM);   // (8, 64)
    gemm_out<<<gout, 256, gemm_smem>>>(oP, woP, out);
}

// round 14
// speedup vs baseline: 1.3925x; 1.0255x over previous
#include <cuda_runtime.h>
#include <cuda_fp16.h>
#include <math.h>

#define BATCH   4
#define TQ      2048
#define TK      2048
#define DMODEL  1024
#define NHEADS  16
#define HDIM    64
#define MROWS   (BATCH * TQ)   // 8192
#define LOG2E   1.4426950408889634f

// ---------------- scratch (__device__ globals; no allocation allowed) -------
__device__ __half h_Q[MROWS * DMODEL];   // (b,h,t,hd-interleaved), prescaled log2e/8
__device__ __half h_K[MROWS * DMODEL];   // (b,h,t,hd-interleaved)
__device__ __half h_V[MROWS * DMODEL];   // (b,h,hd,t-interleaved)  (V^T)
__device__ __half h_O[MROWS * DMODEL];   // (b,t,dmodel-interleaved)
__device__ __half h_Xq[MROWS * DMODEL];
__device__ __half h_Xkv[MROWS * DMODEL];
__device__ __half h_Wq[DMODEL * DMODEL];
__device__ __half h_Wk[DMODEL * DMODEL];
__device__ __half h_Wv[DMODEL * DMODEL];
__device__ __half h_Wo[DMODEL * DMODEL];
__device__ __half h_Mask[TQ * TK];       // additive mask, fp16
__device__ int    g_flags;               // bit0: mask nonzero, bit1: kpm nonzero

// ---------------- helpers ----------------------------------------------------
__device__ __forceinline__ void mma_f16(float* d, const unsigned* a, const unsigned* b) {
    asm volatile(
        "mma.sync.aligned.m16n8k16.row.col.f32.f16.f16.f32 "
        "{%0,%1,%2,%3}, {%4,%5,%6,%7}, {%8,%9}, {%0,%1,%2,%3};"
        : "+f"(d[0]), "+f"(d[1]), "+f"(d[2]), "+f"(d[3])
        : "r"(a[0]), "r"(a[1]), "r"(a[2]), "r"(a[3]), "r"(b[0]), "r"(b[1]));
}

__device__ __forceinline__ void cp16(void* smem_dst, const void* gmem_src) {
    unsigned s = (unsigned)__cvta_generic_to_shared(smem_dst);
    asm volatile("cp.async.cg.shared.global [%0], [%1], 16;" :: "r"(s), "l"(gmem_src));
}

__device__ __forceinline__ float ex2f(float x) {
    float r;
    asm("ex2.approx.f32 %0, %1;" : "=f"(r) : "f"(x));
    return r;
}

__device__ __forceinline__ int islot(int j) { return (j < 4) ? 2 * j : 2 * j - 7; }

// ---------------- pre-convert --------------------------------------------------
__device__ __forceinline__ void cvt_body(const float* __restrict__ src,
                                         __half* __restrict__ dst, int i8, float scale)
{
    float4 v0 = *(const float4*)&src[i8];
    float4 v1 = *(const float4*)&src[i8 + 4];
    int base2 = (i8 & ~15) >> 1;
    int hi = (i8 & 15) ? 1 : 0;
    __half2* d = (__half2*)dst;
    d[base2 + 0 + hi] = __floats2half2_rn(v0.x * scale, v0.y * scale);
    d[base2 + 2 + hi] = __floats2half2_rn(v0.z * scale, v0.w * scale);
    d[base2 + 4 + hi] = __floats2half2_rn(v1.x * scale, v1.y * scale);
    d[base2 + 6 + hi] = __floats2half2_rn(v1.z * scale, v1.w * scale);
}

// ONE launch converts x_q, x_kv (interleaved) and all 4 weights; resets flags.
// Block ranges: [0,4096) xq, [4096,8192) xkv, then 4x512 weight blocks.
__global__ void cvt_all_kernel(const float* xq, const float* xkv,
                               const float* w0, const float* w1,
                               const float* w2, const float* w3,
                               __half* dxq, __half* dxkv,
                               __half* d0, __half* d1, __half* d2, __half* d3,
                               int* flags)
{
    if (blockIdx.x == 0 && threadIdx.x == 0) *flags = 0;
    const int XB = (MROWS * DMODEL) / 8 / 256;   // 4096
    const int WB = (DMODEL * DMODEL) / 8 / 256;  // 512
    int bid = blockIdx.x;
    const float* s; __half* d; int i8;
    if (bid < XB) {
        s = xq;  d = dxq;  i8 = bid * 2048 + threadIdx.x * 8;
    } else if (bid < 2 * XB) {
        s = xkv; d = dxkv; i8 = (bid - XB) * 2048 + threadIdx.x * 8;
    } else {
        int wb = bid - 2 * XB;
        int wi = wb / WB;
        i8 = (wb % WB) * 2048 + threadIdx.x * 8;
        s = (wi == 0) ? w0 : (wi == 1) ? w1 : (wi == 2) ? w2 : w3;
        d = (wi == 0) ? d0 : (wi == 1) ? d1 : (wi == 2) ? d2 : d3;
    }
    cvt_body(s, d, i8, 1.0f);
}

// ---------------- fp16 GEMM core: 128x128x64, 256 thr, 8 warps of 64x32 --------
#define BM   128
#define BN   128
#define BKH  64
#define GST  80     // halves; 40 words = 8 mod 32 -> conflict-free LDS.64

__device__ __forceinline__ void gemm_core(
    const __half* __restrict__ A, const __half* __restrict__ W,
    void* __restrict__ Cv, float scale, int mode, int bm, int bn)
{
    extern __shared__ __half smh[];
    __half* As = smh;                      // [2][BM][GST]
    __half* Ws = smh + 2 * BM * GST;       // [2][BN][GST]

    const int tid  = threadIdx.x;
    const int lane = tid & 31;
    const int warp = tid >> 5;
    const int wm   = warp >> 2;
    const int wn   = warp & 3;
    const int lr   = lane >> 2;
    const int lc   = lane & 3;

    float acc[4][4][4];
#pragma unroll
    for (int i = 0; i < 4; i++)
#pragma unroll
        for (int j = 0; j < 4; j++)
#pragma unroll
            for (int c = 0; c < 4; c++) acc[i][j][c] = 0.f;

    const int NIT = DMODEL / BKH;  // 16

    auto load_stage = [&](int st, int k0) {
#pragma unroll
        for (int r = 0; r < 4; r++) {
            int id  = tid + r * 256;
            int m   = id >> 3;
            int c8  = (id & 7) * 8;
            cp16(&As[(st * BM + m) * GST + c8], &A[(size_t)(bm + m) * DMODEL + k0 + c8]);
        }
#pragma unroll
        for (int r = 0; r < 4; r++) {
            int id  = tid + r * 256;
            int m   = id >> 3;
            int c8  = (id & 7) * 8;
            cp16(&Ws[(st * BN + m) * GST + c8], &W[(size_t)(bn + m) * DMODEL + k0 + c8]);
        }
        asm volatile("cp.async.commit_group;");
    };

    load_stage(0, 0);

    for (int it = 0; it < NIT; it++) {
        if (it + 1 < NIT) {
            load_stage((it + 1) & 1, (it + 1) * BKH);
            asm volatile("cp.async.wait_group 1;");
        } else {
            asm volatile("cp.async.wait_group 0;");
        }
        __syncthreads();
        const __half* Ab = &As[(it & 1) * BM * GST];
        const __half* Wb = &Ws[(it & 1) * BN * GST];

#pragma unroll
        for (int kk = 0; kk < 4; kk++) {
            unsigned af[4][4], bf[4][2];
#pragma unroll
            for (int mf = 0; mf < 4; mf++) {
                const int row = wm * 64 + mf * 16 + lr;
                uint2 u0 = *(const uint2*)&Ab[row * GST + kk * 16 + 4 * lc];
                uint2 u1 = *(const uint2*)&Ab[(row + 8) * GST + kk * 16 + 4 * lc];
                af[mf][0] = u0.x; af[mf][1] = u1.x; af[mf][2] = u0.y; af[mf][3] = u1.y;
            }
#pragma unroll
            for (int nf = 0; nf < 4; nf++) {
                const int row = wn * 32 + nf * 8 + lr;
                uint2 u = *(const uint2*)&Wb[row * GST + kk * 16 + 4 * lc];
                bf[nf][0] = u.x; bf[nf][1] = u.y;
            }
#pragma unroll
            for (int mf = 0; mf < 4; mf++)
#pragma unroll
                for (int nf = 0; nf < 4; nf++)
                    mma_f16(acc[mf][nf], af[mf], bf[nf]);
        }
        __syncthreads();
    }

    // epilogue
#pragma unroll
    for (int mf = 0; mf < 4; mf++) {
#pragma unroll
        for (int half = 0; half < 2; half++) {
            const int m = bm + wm * 64 + mf * 16 + lr + half * 8;
#pragma unroll
            for (int nf = 0; nf < 4; nf++) {
                const int n = bn + wn * 32 + nf * 8 + 2 * lc;
                float c0 = acc[mf][nf][half * 2], c1 = acc[mf][nf][half * 2 + 1];
                if (mode == 0) {
                    float* C = (float*)Cv;
                    *(float2*)&C[(size_t)m * DMODEL + n] = make_float2(c0, c1);
                } else if (mode == 1) {
                    __half* C = (__half*)Cv;
                    const int b = m >> 11, t = m & 2047;
                    const int h = n >> 6;
                    const int hd = n & 63;
                    const int offd = (hd & ~15) + 2 * islot((hd & 15) >> 1);
                    __half2 hv = __floats2half2_rn(c0 * scale, c1 * scale);
                    *(__half2*)&C[(((size_t)(b * NHEADS + h) * TQ + t) << 6) + offd] = hv;
                } else {
                    __half* C = (__half*)Cv;
                    const int b = m >> 11, t = m & 2047;
                    const int h = n >> 6;
                    const int hd0 = n & 63;
                    const int col = (t & ~15) + 2 * islot((t & 15) >> 1) + (t & 1);
                    __half* base = &C[((size_t)(b * NHEADS + h) * HDIM) * (size_t)TK];
                    base[(size_t)hd0 * TK + col]       = __float2half_rn(c0);
                    base[(size_t)(hd0 + 1) * TK + col] = __float2half_rn(c1);
                }
            }
        }
    }
}

// fused Q/K/V projections + mask/kpm preprocessing (grid.z == 3 slice)
__global__ void __launch_bounds__(256, 2)
gemm_qkv(const __half* __restrict__ xq, const __half* __restrict__ xkv,
         const __half* __restrict__ wq, const __half* __restrict__ wk,
         const __half* __restrict__ wv,
         __half* __restrict__ qP, __half* __restrict__ kP, __half* __restrict__ vP,
         float qscale,
         const float* __restrict__ maskF, __half* __restrict__ maskH,
         const unsigned char* __restrict__ kpm, int* __restrict__ flags)
{
    const int bm = blockIdx.y * BM;
    const int bn = blockIdx.x * BN;
    if (blockIdx.z == 0)      { gemm_core(xq,  wq, qP, qscale, 1, bm, bn); return; }
    else if (blockIdx.z == 1) { gemm_core(xkv, wk, kP, 1.0f,   1, bm, bn); return; }
    else if (blockIdx.z == 2) { gemm_core(xkv, wv, vP, 1.0f,   2, bm, bn); return; }

    // z == 3: mask fp32->fp16 + nonzero detect, plus kpm any-true detect.
    const int base = blockIdx.y * gridDim.x + blockIdx.x;   // 0..511
    bool nz = false;
#pragma unroll
    for (int r = 0; r < 4; r++) {
        int i8 = (base * 1024 + r * 256 + threadIdx.x) * 8;
        float4 v0 = *(const float4*)&maskF[i8];
        float4 v1 = *(const float4*)&maskF[i8 + 4];
        __half2 h[4];
        h[0] = __floats2half2_rn(v0.x, v0.y);
        h[1] = __floats2half2_rn(v0.z, v0.w);
        h[2] = __floats2half2_rn(v1.x, v1.y);
        h[3] = __floats2half2_rn(v1.z, v1.w);
        *(uint4*)&maskH[i8] = *(uint4*)h;
        nz |= (v0.x != 0.f) | (v0.y != 0.f) | (v0.z != 0.f) | (v0.w != 0.f) |
              (v1.x != 0.f) | (v1.y != 0.f) | (v1.z != 0.f) | (v1.w != 0.f);
    }
    if (__ballot_sync(0xffffffffu, nz)) {
        if ((threadIdx.x & 31) == 0) atomicOr(flags, 1);
    }
    if (base == 0) {
        bool knz = false;
#pragma unroll
        for (int r = 0; r < 2; r++) {
            int i16 = (r * 256 + threadIdx.x) * 16;     // covers 8192 bytes
            uint4 v = *(const uint4*)&kpm[i16];
            knz |= ((v.x | v.y | v.z | v.w) != 0u);
        }
        if (__ballot_sync(0xffffffffu, knz)) {
            if ((threadIdx.x & 31) == 0) atomicOr(flags, 2);
        }
    }
}

// final output projection (fp32 out)
__global__ void __launch_bounds__(256, 2)
gemm_out(const __half* __restrict__ A, const __half* __restrict__ W,
         float* __restrict__ C)
{
    gemm_core(A, W, C, 1.0f, 0, blockIdx.y * BM, blockIdx.x * BN);
}

// ---------------- fused attention, fp16 mma, log2-domain softmax ----------------
#define AQ   64
#define KT   64
#define ASTR 80

__global__ void __launch_bounds__(128, 3)
attn_h16(const __half* __restrict__ Q, const __half* __restrict__ K,
         const __half* __restrict__ V, const __half* __restrict__ mask,
         const unsigned char* __restrict__ kpm, __half* __restrict__ O,
         const int* __restrict__ flagsP)
{
    extern __shared__ __half smh[];
    __half* Qs = smh;                      // 64 x 80
    __half* Ks = smh + AQ * ASTR;          // [2][64][80]
    __half* Vs = Ks + 2 * KT * ASTR;       // [2][64][80] (V^T)

    const int tid  = threadIdx.x;
    const int lane = tid & 31;
    const int warp = tid >> 5;
    const int lr   = lane >> 2;
    const int lc   = lane & 3;

    const int q0 = blockIdx.x * AQ;
    const int bh = blockIdx.y;
    const int b  = bh >> 4;
    const int h  = bh & 15;

    const bool plain = (*flagsP == 0);

    const __half* Qb = Q + (size_t)bh * TQ * HDIM;
    const __half* Kb = K + (size_t)bh * TK * HDIM;
    const __half* Vb = V + (size_t)bh * HDIM * TK;

#pragma unroll
    for (int r = 0; r < 4; r++) {
        int id = tid + r * 128;
        int row = id >> 3, c8 = (id & 7) * 8;
        cp16(&Qs[row * ASTR + c8], &Qb[(size_t)(q0 + row) * HDIM + c8]);
    }
    asm volatile("cp.async.commit_group;");

    auto cp_KV = [&](int st, int kt) {
        const int k0 = kt * KT;
#pragma unroll
        for (int r = 0; r < 4; r++) {
            int id = tid + r * 128;
            int row = id >> 3, c8 = (id & 7) * 8;
            cp16(&Ks[st * KT * ASTR + row * ASTR + c8], &Kb[(size_t)(k0 + row) * HDIM + c8]);
        }
#pragma unroll
        for (int r = 0; r < 4; r++) {
            int id = tid + r * 128;
            int row = id >> 3, c8 = (id & 7) * 8;   // row = hd
            cp16(&Vs[st * KT * ASTR + row * ASTR + c8], &Vb[(size_t)row * TK + k0 + c8]);
        }
        asm volatile("cp.async.commit_group;");
    };

    cp_KV(0, 0);

    asm volatile("cp.async.wait_group 1;");
    __syncthreads();

    unsigned qf[4][4];
#pragma unroll
    for (int kk = 0; kk < 4; kk++) {
        const int row = warp * 16 + lr;
        uint2 u0 = *(const uint2*)&Qs[row * ASTR + kk * 16 + 4 * lc];
        uint2 u1 = *(const uint2*)&Qs[(row + 8) * ASTR + kk * 16 + 4 * lc];
        qf[kk][0] = u0.x; qf[kk][1] = u1.x; qf[kk][2] = u0.y; qf[kk][3] = u1.y;
    }

    float m_i[2] = {-INFINITY, -INFINITY};
    float l_i[2] = {0.f, 0.f};
    float o[8][4];
#pragma unroll
    for (int nf = 0; nf < 8; nf++)
#pragma unroll
        for (int c = 0; c < 4; c++) o[nf][c] = 0.f;

    const int NT = TK / KT;   // 32
    for (int kt = 0; kt < NT; kt++) {
        const int k0 = kt * KT;

        asm volatile("cp.async.wait_group 0;");
        __syncthreads();

        if (kt + 1 < NT) cp_KV((kt + 1) & 1, kt + 1);

        const __half* Kst = &Ks[(kt & 1) * KT * ASTR];
        const __half* Vst = &Vs[(kt & 1) * KT * ASTR];

        // S = Q @ K^T  (log2 domain)
        float s[8][4];
#pragma unroll
        for (int nf = 0; nf < 8; nf++)
#pragma unroll
            for (int c = 0; c < 4; c++) s[nf][c] = 0.f;

#pragma unroll
        for (int kk = 0; kk < 4; kk++) {
#pragma unroll
            for (int nf = 0; nf < 8; nf++) {
                unsigned bf[2];
                uint2 u = *(const uint2*)&Kst[(nf * 8 + lr) * ASTR + kk * 16 + 4 * lc];
                bf[0] = u.x; bf[1] = u.y;
                mma_f16(s[nf], qf[kk], bf);
            }
        }

        if (!plain) {
            uchar2 kp[8];
#pragma unroll
            for (int nf = 0; nf < 8; nf++)
                kp[nf] = *(const uchar2*)&kpm[(size_t)b * TK + k0 + nf * 8 + 2 * lc];
#pragma unroll
            for (int hf = 0; hf < 2; hf++) {
                const int qg = q0 + warp * 16 + lr + hf * 8;
                const __half* mrow = &mask[(size_t)qg * TK + k0];
#pragma unroll
                for (int nf = 0; nf < 8; nf++) {
                    float2 mv = __half22float2(*(const __half2*)&mrow[nf * 8 + 2 * lc]);
                    float v0 = s[nf][hf * 2]     + mv.x * LOG2E;
                    float v1 = s[nf][hf * 2 + 1] + mv.y * LOG2E;
                    if (kp[nf].x) v0 = -INFINITY;
                    if (kp[nf].y) v1 = -INFINITY;
                    s[nf][hf * 2]     = v0;
                    s[nf][hf * 2 + 1] = v1;
                }
            }
        }

        // online softmax (log2 domain) -> packed fp16 P fragments
        unsigned e[8][2];
#pragma unroll
        for (int hf = 0; hf < 2; hf++) {
            float mx = -INFINITY;
#pragma unroll
            for (int nf = 0; nf < 8; nf++)
                mx = fmaxf(mx, fmaxf(s[nf][hf * 2], s[nf][hf * 2 + 1]));
            mx = fmaxf(mx, __shfl_xor_sync(0xffffffffu, mx, 1));
            mx = fmaxf(mx, __shfl_xor_sync(0xffffffffu, mx, 2));
            float mnew = fmaxf(m_i[hf], mx);
            float alpha, rs = 0.f;
            if (mnew == -INFINITY) {
                alpha = 1.f;
#pragma unroll
                for (int nf = 0; nf < 8; nf++) e[nf][hf] = 0u;
            } else {
                alpha = ex2f(m_i[hf] - mnew);
#pragma unroll
                for (int nf = 0; nf < 8; nf++) {
                    __half2 xh = __floats2half2_rn(s[nf][hf * 2] - mnew,
                                                   s[nf][hf * 2 + 1] - mnew);
                    __half2 ph = h2exp2(xh);
                    e[nf][hf] = *(unsigned*)&ph;
                    float2 pf = __half22float2(ph);
                    rs += pf.x + pf.y;
                }
            }
            rs += __shfl_xor_sync(0xffffffffu, rs, 1);
            rs += __shfl_xor_sync(0xffffffffu, rs, 2);
            l_i[hf] = l_i[hf] * alpha + rs;
            m_i[hf] = mnew;
#pragma unroll
            for (int nf = 0; nf < 8; nf++) {
                o[nf][hf * 2]     *= alpha;
                o[nf][hf * 2 + 1] *= alpha;
            }
        }

        // O += P @ V
#pragma unroll
        for (int kb = 0; kb < 4; kb++) {
            unsigned af[4];
            af[0] = e[2 * kb][0];
            af[1] = e[2 * kb][1];
            af[2] = e[2 * kb + 1][0];
            af[3] = e[2 * kb + 1][1];
#pragma unroll
            for (int nf = 0; nf < 8; nf++) {
                unsigned bf[2];
                uint2 u = *(const uint2*)&Vst[(nf * 8 + lr) * ASTR + kb * 16 + 4 * lc];
                bf[0] = u.x; bf[1] = u.y;
                mma_f16(o[nf], af, bf);
            }
        }
    }

    // finalize: (b,t,dmodel-interleaved) fp16
#pragma unroll
    for (int hf = 0; hf < 2; hf++) {
        const float inv = (l_i[hf] > 0.f) ? (1.f / l_i[hf]) : 0.f;
        const int t = q0 + warp * 16 + lr + hf * 8;
#pragma unroll
        for (int nf = 0; nf < 8; nf++) {
            const int n = h * HDIM + nf * 8 + 2 * lc;
            const int offd = (n & ~15) + 2 * islot((n & 15) >> 1);
            __half2 hv = __floats2half2_rn(o[nf][hf * 2] * inv, o[nf][hf * 2 + 1] * inv);
            *(__half2*)&O[((size_t)(b * TQ + t)) * DMODEL + offd] = hv;
        }
    }
}

// ---------------- launch --------------------------------------------------------
extern "C" void kernel_launch(void* const* d_in, const int* in_sizes, int n_in,
                              void* d_out, int out_size)
{
    const float* x_q   = (const float*)d_in[0];
    const float* x_kv  = (const float*)d_in[1];
    const float* amask = (const float*)d_in[2];
    const unsigned char* kpm = (const unsigned char*)d_in[3];
    const float* Wq = (const float*)d_in[4];
    const float* Wk = (const float*)d_in[5];
    const float* Wv = (const float*)d_in[6];
    const float* Wo = (const float*)d_in[7];
    float* out = (float*)d_out;

    __half *qP, *kP, *vP, *oP, *xqP, *xkvP, *wqP, *wkP, *wvP, *woP, *mP;
    int* flagsP;
    cudaGetSymbolAddress((void**)&qP,  h_Q);
    cudaGetSymbolAddress((void**)&kP,  h_K);
    cudaGetSymbolAddress((void**)&vP,  h_V);
    cudaGetSymbolAddress((void**)&oP,  h_O);
    cudaGetSymbolAddress((void**)&xqP, h_Xq);
    cudaGetSymbolAddress((void**)&xkvP,h_Xkv);
    cudaGetSymbolAddress((void**)&wqP, h_Wq);
    cudaGetSymbolAddress((void**)&wkP, h_Wk);
    cudaGetSymbolAddress((void**)&wvP, h_Wv);
    cudaGetSymbolAddress((void**)&woP, h_Wo);
    cudaGetSymbolAddress((void**)&mP,  h_Mask);
    cudaGetSymbolAddress((void**)&flagsP, g_flags);

    // single fused conversion launch: xq, xkv, 4 weights (+ flags reset)
    const int XB = (MROWS * DMODEL) / 8 / 256;   // 4096
    const int WB = (DMODEL * DMODEL) / 8 / 256;  // 512
    cvt_all_kernel<<<2 * XB + 4 * WB, 256>>>(x_q, x_kv, Wq, Wk, Wv, Wo,
                                             xqP, xkvP, wqP, wkP, wvP, woP, flagsP);

    const int gemm_smem = 2 * (BM + BN) * GST * (int)sizeof(__half);   // 81920
    cudaFuncSetAttribute(gemm_qkv, cudaFuncAttributeMaxDynamicSharedMemorySize, gemm_smem);
    cudaFuncSetAttribute(gemm_out, cudaFuncAttributeMaxDynamicSharedMemorySize, gemm_smem);

    const float qscale = 0.125f * LOG2E;

    // z = 0..2: Q/K/V projections; z = 3: mask cvt + kpm check (rides GEMM slack)
    dim3 gqkv(DMODEL / BN, MROWS / BM, 4);   // (8, 64, 4)
    gemm_qkv<<<gqkv, 256, gemm_smem>>>(xqP, xkvP, wqP, wkP, wvP, qP, kP, vP, qscale,
                                       amask, mP, kpm, flagsP);

    const int attn_smem = 5 * KT * ASTR * (int)sizeof(__half);   // 51200
    cudaFuncSetAttribute(attn_h16, cudaFuncAttributeMaxDynamicSharedMemorySize, attn_smem);
    dim3 ga(TQ / AQ, BATCH * NHEADS);     // (32, 64)
    attn_h16<<<ga, 128, attn_smem>>>(qP, kP, vP, mP, kpm, oP, flagsP);

    dim3 gout(DMODEL / BN, MROWS / BM);   // (8, 64)
    gemm_out<<<gout, 256, gemm_smem>>>(oP, woP, out);
}

// round 15
// speedup vs baseline: 1.4177x; 1.0182x over previous
#include <cuda_runtime.h>
#include <cuda_fp16.h>
#include <math.h>

#define BATCH   4
#define TQ      2048
#define TK      2048
#define DMODEL  1024
#define NHEADS  16
#define HDIM    64
#define MROWS   (BATCH * TQ)   // 8192
#define LOG2E   1.4426950408889634f

// ---------------- scratch (__device__ globals; no allocation allowed) -------
__device__ __half h_Q[MROWS * DMODEL];   // (b,h,t,hd-interleaved), prescaled log2e/8
__device__ __half h_K[MROWS * DMODEL];   // (b,h,t,hd-interleaved)
__device__ __half h_V[MROWS * DMODEL];   // (b,h,hd,t-interleaved)  (V^T)
__device__ __half h_O[MROWS * DMODEL];   // (b,t,dmodel-interleaved)
__device__ __half h_Xq[MROWS * DMODEL];
__device__ __half h_Xkv[MROWS * DMODEL];
__device__ __half h_Wq[DMODEL * DMODEL];
__device__ __half h_Wk[DMODEL * DMODEL];
__device__ __half h_Wv[DMODEL * DMODEL];
__device__ __half h_Wo[DMODEL * DMODEL];
__device__ __half h_Mask[TQ * TK];       // additive mask, fp16
__device__ int    g_flags;               // bit0: mask nonzero, bit1: kpm nonzero

// ---------------- helpers ----------------------------------------------------
__device__ __forceinline__ void mma_f16(float* d, const unsigned* a, const unsigned* b) {
    asm volatile(
        "mma.sync.aligned.m16n8k16.row.col.f32.f16.f16.f32 "
        "{%0,%1,%2,%3}, {%4,%5,%6,%7}, {%8,%9}, {%0,%1,%2,%3};"
        : "+f"(d[0]), "+f"(d[1]), "+f"(d[2]), "+f"(d[3])
        : "r"(a[0]), "r"(a[1]), "r"(a[2]), "r"(a[3]), "r"(b[0]), "r"(b[1]));
}

__device__ __forceinline__ void cp16(void* smem_dst, const void* gmem_src) {
    unsigned s = (unsigned)__cvta_generic_to_shared(smem_dst);
    asm volatile("cp.async.cg.shared.global [%0], [%1], 16;" :: "r"(s), "l"(gmem_src));
}

__device__ __forceinline__ float ex2f(float x) {
    float r;
    asm("ex2.approx.f32 %0, %1;" : "=f"(r) : "f"(x));
    return r;
}

__device__ __forceinline__ int islot(int j) { return (j < 4) ? 2 * j : 2 * j - 7; }

// ---------------- pre-convert --------------------------------------------------
__device__ __forceinline__ void cvt_body(const float* __restrict__ src,
                                         __half* __restrict__ dst, int i8, float scale)
{
    float4 v0 = *(const float4*)&src[i8];
    float4 v1 = *(const float4*)&src[i8 + 4];
    int base2 = (i8 & ~15) >> 1;
    int hi = (i8 & 15) ? 1 : 0;
    __half2* d = (__half2*)dst;
    d[base2 + 0 + hi] = __floats2half2_rn(v0.x * scale, v0.y * scale);
    d[base2 + 2 + hi] = __floats2half2_rn(v0.z * scale, v0.w * scale);
    d[base2 + 4 + hi] = __floats2half2_rn(v1.x * scale, v1.y * scale);
    d[base2 + 6 + hi] = __floats2half2_rn(v1.z * scale, v1.w * scale);
}

__global__ void cvt_all_kernel(const float* xq, const float* xkv,
                               const float* w0, const float* w1,
                               const float* w2, const float* w3,
                               __half* dxq, __half* dxkv,
                               __half* d0, __half* d1, __half* d2, __half* d3,
                               int* flags)
{
    if (blockIdx.x == 0 && threadIdx.x == 0) *flags = 0;
    const int XB = (MROWS * DMODEL) / 8 / 256;   // 4096
    const int WB = (DMODEL * DMODEL) / 8 / 256;  // 512
    int bid = blockIdx.x;
    const float* s; __half* d; int i8;
    if (bid < XB) {
        s = xq;  d = dxq;  i8 = bid * 2048 + threadIdx.x * 8;
    } else if (bid < 2 * XB) {
        s = xkv; d = dxkv; i8 = (bid - XB) * 2048 + threadIdx.x * 8;
    } else {
        int wb = bid - 2 * XB;
        int wi = wb / WB;
        i8 = (wb % WB) * 2048 + threadIdx.x * 8;
        s = (wi == 0) ? w0 : (wi == 1) ? w1 : (wi == 2) ? w2 : w3;
        d = (wi == 0) ? d0 : (wi == 1) ? d1 : (wi == 2) ? d2 : d3;
    }
    cvt_body(s, d, i8, 1.0f);
}

// ---------------- fp16 GEMM core: 128x128x64, 256 thr, 8 warps of 64x32 --------
#define BM   128
#define BN   128
#define BKH  64
#define GST  80

__device__ __forceinline__ void gemm_core(
    const __half* __restrict__ A, const __half* __restrict__ W,
    void* __restrict__ Cv, float scale, int mode, int bm, int bn)
{
    extern __shared__ __half smh[];
    __half* As = smh;
    __half* Ws = smh + 2 * BM * GST;

    const int tid  = threadIdx.x;
    const int lane = tid & 31;
    const int warp = tid >> 5;
    const int wm   = warp >> 2;
    const int wn   = warp & 3;
    const int lr   = lane >> 2;
    const int lc   = lane & 3;

    float acc[4][4][4];
#pragma unroll
    for (int i = 0; i < 4; i++)
#pragma unroll
        for (int j = 0; j < 4; j++)
#pragma unroll
            for (int c = 0; c < 4; c++) acc[i][j][c] = 0.f;

    const int NIT = DMODEL / BKH;

    auto load_stage = [&](int st, int k0) {
#pragma unroll
        for (int r = 0; r < 4; r++) {
            int id  = tid + r * 256;
            int m   = id >> 3;
            int c8  = (id & 7) * 8;
            cp16(&As[(st * BM + m) * GST + c8], &A[(size_t)(bm + m) * DMODEL + k0 + c8]);
        }
#pragma unroll
        for (int r = 0; r < 4; r++) {
            int id  = tid + r * 256;
            int m   = id >> 3;
            int c8  = (id & 7) * 8;
            cp16(&Ws[(st * BN + m) * GST + c8], &W[(size_t)(bn + m) * DMODEL + k0 + c8]);
        }
        asm volatile("cp.async.commit_group;");
    };

    load_stage(0, 0);

    for (int it = 0; it < NIT; it++) {
        if (it + 1 < NIT) {
            load_stage((it + 1) & 1, (it + 1) * BKH);
            asm volatile("cp.async.wait_group 1;");
        } else {
            asm volatile("cp.async.wait_group 0;");
        }
        __syncthreads();
        const __half* Ab = &As[(it & 1) * BM * GST];
        const __half* Wb = &Ws[(it & 1) * BN * GST];

#pragma unroll
        for (int kk = 0; kk < 4; kk++) {
            unsigned af[4][4], bf[4][2];
#pragma unroll
            for (int mf = 0; mf < 4; mf++) {
                const int row = wm * 64 + mf * 16 + lr;
                uint2 u0 = *(const uint2*)&Ab[row * GST + kk * 16 + 4 * lc];
                uint2 u1 = *(const uint2*)&Ab[(row + 8) * GST + kk * 16 + 4 * lc];
                af[mf][0] = u0.x; af[mf][1] = u1.x; af[mf][2] = u0.y; af[mf][3] = u1.y;
            }
#pragma unroll
            for (int nf = 0; nf < 4; nf++) {
                const int row = wn * 32 + nf * 8 + lr;
                uint2 u = *(const uint2*)&Wb[row * GST + kk * 16 + 4 * lc];
                bf[nf][0] = u.x; bf[nf][1] = u.y;
            }
#pragma unroll
            for (int mf = 0; mf < 4; mf++)
#pragma unroll
                for (int nf = 0; nf < 4; nf++)
                    mma_f16(acc[mf][nf], af[mf], bf[nf]);
        }
        __syncthreads();
    }

#pragma unroll
    for (int mf = 0; mf < 4; mf++) {
#pragma unroll
        for (int half = 0; half < 2; half++) {
            const int m = bm + wm * 64 + mf * 16 + lr + half * 8;
#pragma unroll
            for (int nf = 0; nf < 4; nf++) {
                const int n = bn + wn * 32 + nf * 8 + 2 * lc;
                float c0 = acc[mf][nf][half * 2], c1 = acc[mf][nf][half * 2 + 1];
                if (mode == 0) {
                    float* C = (float*)Cv;
                    *(float2*)&C[(size_t)m * DMODEL + n] = make_float2(c0, c1);
                } else if (mode == 1) {
                    __half* C = (__half*)Cv;
                    const int b = m >> 11, t = m & 2047;
                    const int h = n >> 6;
                    const int hd = n & 63;
                    const int offd = (hd & ~15) + 2 * islot((hd & 15) >> 1);
                    __half2 hv = __floats2half2_rn(c0 * scale, c1 * scale);
                    *(__half2*)&C[(((size_t)(b * NHEADS + h) * TQ + t) << 6) + offd] = hv;
                } else {
                    __half* C = (__half*)Cv;
                    const int b = m >> 11, t = m & 2047;
                    const int h = n >> 6;
                    const int hd0 = n & 63;
                    const int col = (t & ~15) + 2 * islot((t & 15) >> 1) + (t & 1);
                    __half* base = &C[((size_t)(b * NHEADS + h) * HDIM) * (size_t)TK];
                    base[(size_t)hd0 * TK + col]       = __float2half_rn(c0);
                    base[(size_t)(hd0 + 1) * TK + col] = __float2half_rn(c1);
                }
            }
        }
    }
}

__global__ void __launch_bounds__(256, 2)
gemm_qkv(const __half* __restrict__ xq, const __half* __restrict__ xkv,
         const __half* __restrict__ wq, const __half* __restrict__ wk,
         const __half* __restrict__ wv,
         __half* __restrict__ qP, __half* __restrict__ kP, __half* __restrict__ vP,
         float qscale,
         const float* __restrict__ maskF, __half* __restrict__ maskH,
         const unsigned char* __restrict__ kpm, int* __restrict__ flags)
{
    const int bm = blockIdx.y * BM;
    const int bn = blockIdx.x * BN;
    if (blockIdx.z == 0)      { gemm_core(xq,  wq, qP, qscale, 1, bm, bn); return; }
    else if (blockIdx.z == 1) { gemm_core(xkv, wk, kP, 1.0f,   1, bm, bn); return; }
    else if (blockIdx.z == 2) { gemm_core(xkv, wv, vP, 1.0f,   2, bm, bn); return; }

    const int base = blockIdx.y * gridDim.x + blockIdx.x;   // 0..511
    bool nz = false;
#pragma unroll
    for (int r = 0; r < 4; r++) {
        int i8 = (base * 1024 + r * 256 + threadIdx.x) * 8;
        float4 v0 = *(const float4*)&maskF[i8];
        float4 v1 = *(const float4*)&maskF[i8 + 4];
        __half2 h[4];
        h[0] = __floats2half2_rn(v0.x, v0.y);
        h[1] = __floats2half2_rn(v0.z, v0.w);
        h[2] = __floats2half2_rn(v1.x, v1.y);
        h[3] = __floats2half2_rn(v1.z, v1.w);
        *(uint4*)&maskH[i8] = *(uint4*)h;
        nz |= (v0.x != 0.f) | (v0.y != 0.f) | (v0.z != 0.f) | (v0.w != 0.f) |
              (v1.x != 0.f) | (v1.y != 0.f) | (v1.z != 0.f) | (v1.w != 0.f);
    }
    if (__ballot_sync(0xffffffffu, nz)) {
        if ((threadIdx.x & 31) == 0) atomicOr(flags, 1);
    }
    if (base == 0) {
        bool knz = false;
#pragma unroll
        for (int r = 0; r < 2; r++) {
            int i16 = (r * 256 + threadIdx.x) * 16;
            uint4 v = *(const uint4*)&kpm[i16];
            knz |= ((v.x | v.y | v.z | v.w) != 0u);
        }
        if (__ballot_sync(0xffffffffu, knz)) {
            if ((threadIdx.x & 31) == 0) atomicOr(flags, 2);
        }
    }
}

__global__ void __launch_bounds__(256, 2)
gemm_out(const __half* __restrict__ A, const __half* __restrict__ W,
         float* __restrict__ C)
{
    gemm_core(A, W, C, 1.0f, 0, blockIdx.y * BM, blockIdx.x * BN);
}

// ---------------- fused attention: KT=128, Q in registers -----------------------
// 64 q-rows, 4 warps (16 rows each); K double-buffered (2x128x80), V^T single
// (64x144). 16 key-tiles instead of 32 -> half the softmax/barrier bookkeeping.
#define AQ   64
#define KT   128
#define KSTR 80    // 40 words = 8 mod 32 -> conflict-free LDS.64
#define VSTR 144   // 72 words = 8 mod 32 -> conflict-free LDS.64

__global__ void __launch_bounds__(128, 3)
attn_h16(const __half* __restrict__ Q, const __half* __restrict__ K,
         const __half* __restrict__ V, const __half* __restrict__ mask,
         const unsigned char* __restrict__ kpm, __half* __restrict__ O,
         const int* __restrict__ flagsP)
{
    extern __shared__ __half smh[];
    __half* Ks = smh;                      // [2][128][KSTR]
    __half* Vs = smh + 2 * KT * KSTR;      // [64][VSTR]  (V^T: rows=hd)

    const int tid  = threadIdx.x;
    const int lane = tid & 31;
    const int warp = tid >> 5;
    const int lr   = lane >> 2;
    const int lc   = lane & 3;

    const int q0 = blockIdx.x * AQ;
    const int bh = blockIdx.y;
    const int b  = bh >> 4;
    const int h  = bh & 15;

    const bool plain = (*flagsP == 0);

    const __half* Qb = Q + (size_t)bh * TQ * HDIM;
    const __half* Kb = K + (size_t)bh * TK * HDIM;
    const __half* Vb = V + (size_t)bh * HDIM * TK;

    auto cp_K = [&](int st, int kt) {
        const int k0 = kt * KT;
#pragma unroll
        for (int r = 0; r < 8; r++) {
            int id = tid + r * 128;
            int row = id >> 3, c8 = (id & 7) * 8;
            cp16(&Ks[st * KT * KSTR + row * KSTR + c8], &Kb[(size_t)(k0 + row) * HDIM + c8]);
        }
        asm volatile("cp.async.commit_group;");
    };
    auto cp_V = [&](int kt) {
        const int k0 = kt * KT;
#pragma unroll
        for (int r = 0; r < 8; r++) {
            int id = tid + r * 128;
            int row = id >> 4, c8 = (id & 15) * 8;   // row = hd (0..63), 128 halves/row
            cp16(&Vs[row * VSTR + c8], &Vb[(size_t)row * TK + k0 + c8]);
        }
        asm volatile("cp.async.commit_group;");
    };

    cp_K(0, 0);     // group K0
    cp_V(0);        // group V0
    cp_K(1, 1);     // group K1

    // Q fragments straight from gmem (once per block)
    unsigned qf[4][4];
#pragma unroll
    for (int kk = 0; kk < 4; kk++) {
        const int row = q0 + warp * 16 + lr;
        uint2 u0 = *(const uint2*)&Qb[(size_t)row * HDIM + kk * 16 + 4 * lc];
        uint2 u1 = *(const uint2*)&Qb[(size_t)(row + 8) * HDIM + kk * 16 + 4 * lc];
        qf[kk][0] = u0.x; qf[kk][1] = u1.x; qf[kk][2] = u0.y; qf[kk][3] = u1.y;
    }

    float m_i[2] = {-INFINITY, -INFINITY};
    float l_i[2] = {0.f, 0.f};
    float o[8][4];
#pragma unroll
    for (int nf = 0; nf < 8; nf++)
#pragma unroll
        for (int c = 0; c < 4; c++) o[nf][c] = 0.f;

    const int NT = TK / KT;   // 16
    for (int kt = 0; kt < NT; kt++) {
        const int k0 = kt * KT;

        // K(kt) complete (pending: V(kt) [, K(kt+1)])
        if (kt + 1 < NT) asm volatile("cp.async.wait_group 2;");
        else             asm volatile("cp.async.wait_group 1;");
        __syncthreads();

        const __half* Kst = &Ks[(kt & 1) * KT * KSTR];

        // S = Q @ K^T  (16 n-fragments, log2 domain)
        float s[16][4];
#pragma unroll
        for (int nf = 0; nf < 16; nf++)
#pragma unroll
            for (int c = 0; c < 4; c++) s[nf][c] = 0.f;

#pragma unroll
        for (int kk = 0; kk < 4; kk++) {
#pragma unroll
            for (int nf = 0; nf < 16; nf++) {
                unsigned bf[2];
                uint2 u = *(const uint2*)&Kst[(nf * 8 + lr) * KSTR + kk * 16 + 4 * lc];
                bf[0] = u.x; bf[1] = u.y;
                mma_f16(s[nf], qf[kk], bf);
            }
        }

        if (!plain) {
            uchar2 kp[16];
#pragma unroll
            for (int nf = 0; nf < 16; nf++)
                kp[nf] = *(const uchar2*)&kpm[(size_t)b * TK + k0 + nf * 8 + 2 * lc];
#pragma unroll
            for (int hf = 0; hf < 2; hf++) {
                const int qg = q0 + warp * 16 + lr + hf * 8;
                const __half* mrow = &mask[(size_t)qg * TK + k0];
#pragma unroll
                for (int nf = 0; nf < 16; nf++) {
                    float2 mv = __half22float2(*(const __half2*)&mrow[nf * 8 + 2 * lc]);
                    float v0 = s[nf][hf * 2]     + mv.x * LOG2E;
                    float v1 = s[nf][hf * 2 + 1] + mv.y * LOG2E;
                    if (kp[nf].x) v0 = -INFINITY;
                    if (kp[nf].y) v1 = -INFINITY;
                    s[nf][hf * 2]     = v0;
                    s[nf][hf * 2 + 1] = v1;
                }
            }
        }

        // online softmax (log2 domain) -> packed fp16 P fragments
        unsigned e[16][2];
#pragma unroll
        for (int hf = 0; hf < 2; hf++) {
            float mx = -INFINITY;
#pragma unroll
            for (int nf = 0; nf < 16; nf++)
                mx = fmaxf(mx, fmaxf(s[nf][hf * 2], s[nf][hf * 2 + 1]));
            mx = fmaxf(mx, __shfl_xor_sync(0xffffffffu, mx, 1));
            mx = fmaxf(mx, __shfl_xor_sync(0xffffffffu, mx, 2));
            float mnew = fmaxf(m_i[hf], mx);
            float alpha, rs = 0.f;
            if (mnew == -INFINITY) {
                alpha = 1.f;
#pragma unroll
                for (int nf = 0; nf < 16; nf++) e[nf][hf] = 0u;
            } else {
                alpha = ex2f(m_i[hf] - mnew);
#pragma unroll
                for (int nf = 0; nf < 16; nf++) {
                    __half2 xh = __floats2half2_rn(s[nf][hf * 2] - mnew,
                                                   s[nf][hf * 2 + 1] - mnew);
                    __half2 ph = h2exp2(xh);
                    e[nf][hf] = *(unsigned*)&ph;
                    float2 pf = __half22float2(ph);
                    rs += pf.x + pf.y;
                }
            }
            rs += __shfl_xor_sync(0xffffffffu, rs, 1);
            rs += __shfl_xor_sync(0xffffffffu, rs, 2);
            l_i[hf] = l_i[hf] * alpha + rs;
            m_i[hf] = mnew;
#pragma unroll
            for (int nf = 0; nf < 8; nf++) {
                o[nf][hf * 2]     *= alpha;
                o[nf][hf * 2 + 1] *= alpha;
            }
        }

        // V(kt) complete (pending: [K(kt+1)])
        if (kt + 1 < NT) asm volatile("cp.async.wait_group 1;");
        else             asm volatile("cp.async.wait_group 0;");
        __syncthreads();

        // O += P @ V  (8 k16 blocks)
#pragma unroll
        for (int kb = 0; kb < 8; kb++) {
            unsigned af[4];
            af[0] = e[2 * kb][0];
            af[1] = e[2 * kb][1];
            af[2] = e[2 * kb + 1][0];
            af[3] = e[2 * kb + 1][1];
#pragma unroll
            for (int nf = 0; nf < 8; nf++) {
                unsigned bf[2];
                uint2 u = *(const uint2*)&Vs[(nf * 8 + lr) * VSTR + kb * 16 + 4 * lc];
                bf[0] = u.x; bf[1] = u.y;
                mma_f16(o[nf], af, bf);
            }
        }
        __syncthreads();   // PV reads done before next cp_V overwrites Vs

        // prefetch next tiles: V(kt+1), K(kt+2)
        if (kt + 1 < NT) cp_V(kt + 1);
        if (kt + 2 < NT) cp_K(kt & 1, kt + 2);
    }

    // finalize: (b,t,dmodel-interleaved) fp16
#pragma unroll
    for (int hf = 0; hf < 2; hf++) {
        const float inv = (l_i[hf] > 0.f) ? (1.f / l_i[hf]) : 0.f;
        const int t = q0 + warp * 16 + lr + hf * 8;
#pragma unroll
        for (int nf = 0; nf < 8; nf++) {
            const int n = h * HDIM + nf * 8 + 2 * lc;
            const int offd = (n & ~15) + 2 * islot((n & 15) >> 1);
            __half2 hv = __floats2half2_rn(o[nf][hf * 2] * inv, o[nf][hf * 2 + 1] * inv);
            *(__half2*)&O[((size_t)(b * TQ + t)) * DMODEL + offd] = hv;
        }
    }
}

// ---------------- launch --------------------------------------------------------
extern "C" void kernel_launch(void* const* d_in, const int* in_sizes, int n_in,
                              void* d_out, int out_size)
{
    const float* x_q   = (const float*)d_in[0];
    const float* x_kv  = (const float*)d_in[1];
    const float* amask = (const float*)d_in[2];
    const unsigned char* kpm = (const unsigned char*)d_in[3];
    const float* Wq = (const float*)d_in[4];
    const float* Wk = (const float*)d_in[5];
    const float* Wv = (const float*)d_in[6];
    const float* Wo = (const float*)d_in[7];
    float* out = (float*)d_out;

    __half *qP, *kP, *vP, *oP, *xqP, *xkvP, *wqP, *wkP, *wvP, *woP, *mP;
    int* flagsP;
    cudaGetSymbolAddress((void**)&qP,  h_Q);
    cudaGetSymbolAddress((void**)&kP,  h_K);
    cudaGetSymbolAddress((void**)&vP,  h_V);
    cudaGetSymbolAddress((void**)&oP,  h_O);
    cudaGetSymbolAddress((void**)&xqP, h_Xq);
    cudaGetSymbolAddress((void**)&xkvP,h_Xkv);
    cudaGetSymbolAddress((void**)&wqP, h_Wq);
    cudaGetSymbolAddress((void**)&wkP, h_Wk);
    cudaGetSymbolAddress((void**)&wvP, h_Wv);
    cudaGetSymbolAddress((void**)&woP, h_Wo);
    cudaGetSymbolAddress((void**)&mP,  h_Mask);
    cudaGetSymbolAddress((void**)&flagsP, g_flags);

    const int XB = (MROWS * DMODEL) / 8 / 256;   // 4096
    const int WB = (DMODEL * DMODEL) / 8 / 256;  // 512
    cvt_all_kernel<<<2 * XB + 4 * WB, 256>>>(x_q, x_kv, Wq, Wk, Wv, Wo,
                                             xqP, xkvP, wqP, wkP, wvP, woP, flagsP);

    const int gemm_smem = 2 * (BM + BN) * GST * (int)sizeof(__half);   // 81920
    cudaFuncSetAttribute(gemm_qkv, cudaFuncAttributeMaxDynamicSharedMemorySize, gemm_smem);
    cudaFuncSetAttribute(gemm_out, cudaFuncAttributeMaxDynamicSharedMemorySize, gemm_smem);

    const float qscale = 0.125f * LOG2E;

    dim3 gqkv(DMODEL / BN, MROWS / BM, 4);   // (8, 64, 4)
    gemm_qkv<<<gqkv, 256, gemm_smem>>>(xqP, xkvP, wqP, wkP, wvP, qP, kP, vP, qscale,
                                       amask, mP, kpm, flagsP);

    const int attn_smem = (2 * KT * KSTR + HDIM * VSTR) * (int)sizeof(__half);  // 59392
    cudaFuncSetAttribute(attn_h16, cudaFuncAttributeMaxDynamicSharedMemorySize, attn_smem);
    dim3 ga(TQ / AQ, BATCH * NHEADS);     // (32, 64)
    attn_h16<<<ga, 128, attn_smem>>>(qP, kP, vP, mP, kpm, oP, flagsP);

    dim3 gout(DMODEL / BN, MROWS / BM);   // (8, 64)
    gemm_out<<<gout, 256, gemm_smem>>>(oP, woP, out);
}

// round 16
// speedup vs baseline: 1.4513x; 1.0237x over previous
#include <cuda_runtime.h>
#include <cuda_fp16.h>
#include <math.h>

#define BATCH   4
#define TQ      2048
#define TK      2048
#define DMODEL  1024
#define NHEADS  16
#define HDIM    64
#define MROWS   (BATCH * TQ)   // 8192
#define LOG2E   1.4426950408889634f

// ---------------- scratch (__device__ globals; no allocation allowed) -------
__device__ __half h_Q[MROWS * DMODEL];   // (b,h,t,hd-interleaved), prescaled log2e/8
__device__ __half h_K[MROWS * DMODEL];   // (b,h,t,hd-interleaved)
__device__ __half h_V[MROWS * DMODEL];   // (b,h,hd,t-interleaved)  (V^T)
__device__ __half h_O[MROWS * DMODEL];   // (b,t,dmodel-interleaved)
__device__ __half h_Xq[MROWS * DMODEL];
__device__ __half h_Xkv[MROWS * DMODEL];
__device__ __half h_Wq[DMODEL * DMODEL];
__device__ __half h_Wk[DMODEL * DMODEL];
__device__ __half h_Wv[DMODEL * DMODEL];
__device__ __half h_Wo[DMODEL * DMODEL];
__device__ __half h_Mask[TQ * TK];       // additive mask, fp16
__device__ int    g_flags;               // bit0: mask nonzero, bit1: kpm nonzero

// ---------------- helpers ----------------------------------------------------
__device__ __forceinline__ void mma_f16(float* d, const unsigned* a, const unsigned* b) {
    asm volatile(
        "mma.sync.aligned.m16n8k16.row.col.f32.f16.f16.f32 "
        "{%0,%1,%2,%3}, {%4,%5,%6,%7}, {%8,%9}, {%0,%1,%2,%3};"
        : "+f"(d[0]), "+f"(d[1]), "+f"(d[2]), "+f"(d[3])
        : "r"(a[0]), "r"(a[1]), "r"(a[2]), "r"(a[3]), "r"(b[0]), "r"(b[1]));
}

__device__ __forceinline__ void cp16(void* smem_dst, const void* gmem_src) {
    unsigned s = (unsigned)__cvta_generic_to_shared(smem_dst);
    asm volatile("cp.async.cg.shared.global [%0], [%1], 16;" :: "r"(s), "l"(gmem_src));
}

__device__ __forceinline__ float ex2f(float x) {
    float r;
    asm("ex2.approx.f32 %0, %1;" : "=f"(r) : "f"(x));
    return r;
}

__device__ __forceinline__ int islot(int j) { return (j < 4) ? 2 * j : 2 * j - 7; }

// ---------------- pre-convert --------------------------------------------------
__device__ __forceinline__ void cvt_body(const float* __restrict__ src,
                                         __half* __restrict__ dst, int i8, float scale)
{
    float4 v0 = *(const float4*)&src[i8];
    float4 v1 = *(const float4*)&src[i8 + 4];
    int base2 = (i8 & ~15) >> 1;
    int hi = (i8 & 15) ? 1 : 0;
    __half2* d = (__half2*)dst;
    d[base2 + 0 + hi] = __floats2half2_rn(v0.x * scale, v0.y * scale);
    d[base2 + 2 + hi] = __floats2half2_rn(v0.z * scale, v0.w * scale);
    d[base2 + 4 + hi] = __floats2half2_rn(v1.x * scale, v1.y * scale);
    d[base2 + 6 + hi] = __floats2half2_rn(v1.z * scale, v1.w * scale);
}

__global__ void cvt_all_kernel(const float* xq, const float* xkv,
                               const float* w0, const float* w1,
                               const float* w2, const float* w3,
                               __half* dxq, __half* dxkv,
                               __half* d0, __half* d1, __half* d2, __half* d3,
                               int* flags)
{
    if (blockIdx.x == 0 && threadIdx.x == 0) *flags = 0;
    const int XB = (MROWS * DMODEL) / 8 / 256;   // 4096
    const int WB = (DMODEL * DMODEL) / 8 / 256;  // 512
    int bid = blockIdx.x;
    const float* s; __half* d; int i8;
    if (bid < XB) {
        s = xq;  d = dxq;  i8 = bid * 2048 + threadIdx.x * 8;
    } else if (bid < 2 * XB) {
        s = xkv; d = dxkv; i8 = (bid - XB) * 2048 + threadIdx.x * 8;
    } else {
        int wb = bid - 2 * XB;
        int wi = wb / WB;
        i8 = (wb % WB) * 2048 + threadIdx.x * 8;
        s = (wi == 0) ? w0 : (wi == 1) ? w1 : (wi == 2) ? w2 : w3;
        d = (wi == 0) ? d0 : (wi == 1) ? d1 : (wi == 2) ? d2 : d3;
    }
    cvt_body(s, d, i8, 1.0f);
}

// ---------------- fp16 GEMM core: 128x128x64, 256 thr, 8 warps of 64x32 --------
// Single __syncthreads per K-iteration: compute -> wait -> sync -> prefetch.
#define BM   128
#define BN   128
#define BKH  64
#define GST  80

__device__ __forceinline__ void gemm_core(
    const __half* __restrict__ A, const __half* __restrict__ W,
    void* __restrict__ Cv, float scale, int mode, int bm, int bn)
{
    extern __shared__ __half smh[];
    __half* As = smh;
    __half* Ws = smh + 2 * BM * GST;

    const int tid  = threadIdx.x;
    const int lane = tid & 31;
    const int warp = tid >> 5;
    const int wm   = warp >> 2;
    const int wn   = warp & 3;
    const int lr   = lane >> 2;
    const int lc   = lane & 3;

    float acc[4][4][4];
#pragma unroll
    for (int i = 0; i < 4; i++)
#pragma unroll
        for (int j = 0; j < 4; j++)
#pragma unroll
            for (int c = 0; c < 4; c++) acc[i][j][c] = 0.f;

    const int NIT = DMODEL / BKH;   // 16

    auto load_stage = [&](int st, int k0) {
#pragma unroll
        for (int r = 0; r < 4; r++) {
            int id  = tid + r * 256;
            int m   = id >> 3;
            int c8  = (id & 7) * 8;
            cp16(&As[(st * BM + m) * GST + c8], &A[(size_t)(bm + m) * DMODEL + k0 + c8]);
        }
#pragma unroll
        for (int r = 0; r < 4; r++) {
            int id  = tid + r * 256;
            int m   = id >> 3;
            int c8  = (id & 7) * 8;
            cp16(&Ws[(st * BN + m) * GST + c8], &W[(size_t)(bn + m) * DMODEL + k0 + c8]);
        }
        asm volatile("cp.async.commit_group;");
    };

    // prologue: stages 0 and 1 in flight; stage 0 made visible
    load_stage(0, 0);
    load_stage(1, BKH);
    asm volatile("cp.async.wait_group 1;");
    __syncthreads();

    for (int it = 0; it < NIT; it++) {
        const __half* Ab = &As[(it & 1) * BM * GST];
        const __half* Wb = &Ws[(it & 1) * BN * GST];

#pragma unroll
        for (int kk = 0; kk < 4; kk++) {
            unsigned af[4][4], bf[4][2];
#pragma unroll
            for (int mf = 0; mf < 4; mf++) {
                const int row = wm * 64 + mf * 16 + lr;
                uint2 u0 = *(const uint2*)&Ab[row * GST + kk * 16 + 4 * lc];
                uint2 u1 = *(const uint2*)&Ab[(row + 8) * GST + kk * 16 + 4 * lc];
                af[mf][0] = u0.x; af[mf][1] = u1.x; af[mf][2] = u0.y; af[mf][3] = u1.y;
            }
#pragma unroll
            for (int nf = 0; nf < 4; nf++) {
                const int row = wn * 32 + nf * 8 + lr;
                uint2 u = *(const uint2*)&Wb[row * GST + kk * 16 + 4 * lc];
                bf[nf][0] = u.x; bf[nf][1] = u.y;
            }
#pragma unroll
            for (int mf = 0; mf < 4; mf++)
#pragma unroll
                for (int nf = 0; nf < 4; nf++)
                    mma_f16(acc[mf][nf], af[mf], bf[nf]);
        }

        if (it + 1 < NIT) {
            asm volatile("cp.async.wait_group 0;");  // stage it+1 drained (only pending)
            __syncthreads();  // all warps done reading buf it&1 + stage it+1 visible
            if (it + 2 < NIT) load_stage(it & 1, (it + 2) * BKH);
        }
    }

    // epilogue
#pragma unroll
    for (int mf = 0; mf < 4; mf++) {
#pragma unroll
        for (int half = 0; half < 2; half++) {
            const int m = bm + wm * 64 + mf * 16 + lr + half * 8;
#pragma unroll
            for (int nf = 0; nf < 4; nf++) {
                const int n = bn + wn * 32 + nf * 8 + 2 * lc;
                float c0 = acc[mf][nf][half * 2], c1 = acc[mf][nf][half * 2 + 1];
                if (mode == 0) {
                    float* C = (float*)Cv;
                    *(float2*)&C[(size_t)m * DMODEL + n] = make_float2(c0, c1);
                } else if (mode == 1) {
                    __half* C = (__half*)Cv;
                    const int b = m >> 11, t = m & 2047;
                    const int h = n >> 6;
                    const int hd = n & 63;
                    const int offd = (hd & ~15) + 2 * islot((hd & 15) >> 1);
                    __half2 hv = __floats2half2_rn(c0 * scale, c1 * scale);
                    *(__half2*)&C[(((size_t)(b * NHEADS + h) * TQ + t) << 6) + offd] = hv;
                } else {
                    __half* C = (__half*)Cv;
                    const int b = m >> 11, t = m & 2047;
                    const int h = n >> 6;
                    const int hd0 = n & 63;
                    const int col = (t & ~15) + 2 * islot((t & 15) >> 1) + (t & 1);
                    __half* base = &C[((size_t)(b * NHEADS + h) * HDIM) * (size_t)TK];
                    base[(size_t)hd0 * TK + col]       = __float2half_rn(c0);
                    base[(size_t)(hd0 + 1) * TK + col] = __float2half_rn(c1);
                }
            }
        }
    }
}

__global__ void __launch_bounds__(256, 2)
gemm_qkv(const __half* __restrict__ xq, const __half* __restrict__ xkv,
         const __half* __restrict__ wq, const __half* __restrict__ wk,
         const __half* __restrict__ wv,
         __half* __restrict__ qP, __half* __restrict__ kP, __half* __restrict__ vP,
         float qscale,
         const float* __restrict__ maskF, __half* __restrict__ maskH,
         const unsigned char* __restrict__ kpm, int* __restrict__ flags)
{
    const int bm = blockIdx.y * BM;
    const int bn = blockIdx.x * BN;
    if (blockIdx.z == 0)      { gemm_core(xq,  wq, qP, qscale, 1, bm, bn); return; }
    else if (blockIdx.z == 1) { gemm_core(xkv, wk, kP, 1.0f,   1, bm, bn); return; }
    else if (blockIdx.z == 2) { gemm_core(xkv, wv, vP, 1.0f,   2, bm, bn); return; }

    const int base = blockIdx.y * gridDim.x + blockIdx.x;   // 0..511
    bool nz = false;
#pragma unroll
    for (int r = 0; r < 4; r++) {
        int i8 = (base * 1024 + r * 256 + threadIdx.x) * 8;
        float4 v0 = *(const float4*)&maskF[i8];
        float4 v1 = *(const float4*)&maskF[i8 + 4];
        __half2 h[4];
        h[0] = __floats2half2_rn(v0.x, v0.y);
        h[1] = __floats2half2_rn(v0.z, v0.w);
        h[2] = __floats2half2_rn(v1.x, v1.y);
        h[3] = __floats2half2_rn(v1.z, v1.w);
        *(uint4*)&maskH[i8] = *(uint4*)h;
        nz |= (v0.x != 0.f) | (v0.y != 0.f) | (v0.z != 0.f) | (v0.w != 0.f) |
              (v1.x != 0.f) | (v1.y != 0.f) | (v1.z != 0.f) | (v1.w != 0.f);
    }
    if (__ballot_sync(0xffffffffu, nz)) {
        if ((threadIdx.x & 31) == 0) atomicOr(flags, 1);
    }
    if (base == 0) {
        bool knz = false;
#pragma unroll
        for (int r = 0; r < 2; r++) {
            int i16 = (r * 256 + threadIdx.x) * 16;
            uint4 v = *(const uint4*)&kpm[i16];
            knz |= ((v.x | v.y | v.z | v.w) != 0u);
        }
        if (__ballot_sync(0xffffffffu, knz)) {
            if ((threadIdx.x & 31) == 0) atomicOr(flags, 2);
        }
    }
}

__global__ void __launch_bounds__(256, 2)
gemm_out(const __half* __restrict__ A, const __half* __restrict__ W,
         float* __restrict__ C)
{
    gemm_core(A, W, C, 1.0f, 0, blockIdx.y * BM, blockIdx.x * BN);
}

// ---------------- fused attention: KT=128, Q in registers -----------------------
#define AQ   64
#define KT   128
#define KSTR 80    // 40 words = 8 mod 32 -> conflict-free LDS.64
#define VSTR 144   // 72 words = 8 mod 32 -> conflict-free LDS.64

__global__ void __launch_bounds__(128, 3)
attn_h16(const __half* __restrict__ Q, const __half* __restrict__ K,
         const __half* __restrict__ V, const __half* __restrict__ mask,
         const unsigned char* __restrict__ kpm, __half* __restrict__ O,
         const int* __restrict__ flagsP)
{
    extern __shared__ __half smh[];
    __half* Ks = smh;                      // [2][128][KSTR]
    __half* Vs = smh + 2 * KT * KSTR;      // [64][VSTR]  (V^T: rows=hd)

    const int tid  = threadIdx.x;
    const int lane = tid & 31;
    const int warp = tid >> 5;
    const int lr   = lane >> 2;
    const int lc   = lane & 3;

    const int q0 = blockIdx.x * AQ;
    const int bh = blockIdx.y;
    const int b  = bh >> 4;
    const int h  = bh & 15;

    const bool plain = (*flagsP == 0);

    const __half* Qb = Q + (size_t)bh * TQ * HDIM;
    const __half* Kb = K + (size_t)bh * TK * HDIM;
    const __half* Vb = V + (size_t)bh * HDIM * TK;

    auto cp_K = [&](int st, int kt) {
        const int k0 = kt * KT;
#pragma unroll
        for (int r = 0; r < 8; r++) {
            int id = tid + r * 128;
            int row = id >> 3, c8 = (id & 7) * 8;
            cp16(&Ks[st * KT * KSTR + row * KSTR + c8], &Kb[(size_t)(k0 + row) * HDIM + c8]);
        }
        asm volatile("cp.async.commit_group;");
    };
    auto cp_V = [&](int kt) {
        const int k0 = kt * KT;
#pragma unroll
        for (int r = 0; r < 8; r++) {
            int id = tid + r * 128;
            int row = id >> 4, c8 = (id & 15) * 8;
            cp16(&Vs[row * VSTR + c8], &Vb[(size_t)row * TK + k0 + c8]);
        }
        asm volatile("cp.async.commit_group;");
    };

    cp_K(0, 0);
    cp_V(0);
    cp_K(1, 1);

    unsigned qf[4][4];
#pragma unroll
    for (int kk = 0; kk < 4; kk++) {
        const int row = q0 + warp * 16 + lr;
        uint2 u0 = *(const uint2*)&Qb[(size_t)row * HDIM + kk * 16 + 4 * lc];
        uint2 u1 = *(const uint2*)&Qb[(size_t)(row + 8) * HDIM + kk * 16 + 4 * lc];
        qf[kk][0] = u0.x; qf[kk][1] = u1.x; qf[kk][2] = u0.y; qf[kk][3] = u1.y;
    }

    float m_i[2] = {-INFINITY, -INFINITY};
    float l_i[2] = {0.f, 0.f};
    float o[8][4];
#pragma unroll
    for (int nf = 0; nf < 8; nf++)
#pragma unroll
        for (int c = 0; c < 4; c++) o[nf][c] = 0.f;

    const int NT = TK / KT;   // 16
    for (int kt = 0; kt < NT; kt++) {
        const int k0 = kt * KT;

        if (kt + 1 < NT) asm volatile("cp.async.wait_group 2;");
        else             asm volatile("cp.async.wait_group 1;");
        __syncthreads();

        const __half* Kst = &Ks[(kt & 1) * KT * KSTR];

        float s[16][4];
#pragma unroll
        for (int nf = 0; nf < 16; nf++)
#pragma unroll
            for (int c = 0; c < 4; c++) s[nf][c] = 0.f;

#pragma unroll
        for (int kk = 0; kk < 4; kk++) {
#pragma unroll
            for (int nf = 0; nf < 16; nf++) {
                unsigned bf[2];
                uint2 u = *(const uint2*)&Kst[(nf * 8 + lr) * KSTR + kk * 16 + 4 * lc];
                bf[0] = u.x; bf[1] = u.y;
                mma_f16(s[nf], qf[kk], bf);
            }
        }

        if (!plain) {
            uchar2 kp[16];
#pragma unroll
            for (int nf = 0; nf < 16; nf++)
                kp[nf] = *(const uchar2*)&kpm[(size_t)b * TK + k0 + nf * 8 + 2 * lc];
#pragma unroll
            for (int hf = 0; hf < 2; hf++) {
                const int qg = q0 + warp * 16 + lr + hf * 8;
                const __half* mrow = &mask[(size_t)qg * TK + k0];
#pragma unroll
                for (int nf = 0; nf < 16; nf++) {
                    float2 mv = __half22float2(*(const __half2*)&mrow[nf * 8 + 2 * lc]);
                    float v0 = s[nf][hf * 2]     + mv.x * LOG2E;
                    float v1 = s[nf][hf * 2 + 1] + mv.y * LOG2E;
                    if (kp[nf].x) v0 = -INFINITY;
                    if (kp[nf].y) v1 = -INFINITY;
                    s[nf][hf * 2]     = v0;
                    s[nf][hf * 2 + 1] = v1;
                }
            }
        }

        unsigned e[16][2];
#pragma unroll
        for (int hf = 0; hf < 2; hf++) {
            float mx = -INFINITY;
#pragma unroll
            for (int nf = 0; nf < 16; nf++)
                mx = fmaxf(mx, fmaxf(s[nf][hf * 2], s[nf][hf * 2 + 1]));
            mx = fmaxf(mx, __shfl_xor_sync(0xffffffffu, mx, 1));
            mx = fmaxf(mx, __shfl_xor_sync(0xffffffffu, mx, 2));
            float mnew = fmaxf(m_i[hf], mx);
            float alpha, rs = 0.f;
            if (mnew == -INFINITY) {
                alpha = 1.f;
#pragma unroll
                for (int nf = 0; nf < 16; nf++) e[nf][hf] = 0u;
            } else {
                alpha = ex2f(m_i[hf] - mnew);
#pragma unroll
                for (int nf = 0; nf < 16; nf++) {
                    __half2 xh = __floats2half2_rn(s[nf][hf * 2] - mnew,
                                                   s[nf][hf * 2 + 1] - mnew);
                    __half2 ph = h2exp2(xh);
                    e[nf][hf] = *(unsigned*)&ph;
                    float2 pf = __half22float2(ph);
                    rs += pf.x + pf.y;
                }
            }
            rs += __shfl_xor_sync(0xffffffffu, rs, 1);
            rs += __shfl_xor_sync(0xffffffffu, rs, 2);
            l_i[hf] = l_i[hf] * alpha + rs;
            m_i[hf] = mnew;
#pragma unroll
            for (int nf = 0; nf < 8; nf++) {
                o[nf][hf * 2]     *= alpha;
                o[nf][hf * 2 + 1] *= alpha;
            }
        }

        if (kt + 1 < NT) asm volatile("cp.async.wait_group 1;");
        else             asm volatile("cp.async.wait_group 0;");
        __syncthreads();

#pragma unroll
        for (int kb = 0; kb < 8; kb++) {
            unsigned af[4];
            af[0] = e[2 * kb][0];
            af[1] = e[2 * kb][1];
            af[2] = e[2 * kb + 1][0];
            af[3] = e[2 * kb + 1][1];
#pragma unroll
            for (int nf = 0; nf < 8; nf++) {
                unsigned bf[2];
                uint2 u = *(const uint2*)&Vs[(nf * 8 + lr) * VSTR + kb * 16 + 4 * lc];
                bf[0] = u.x; bf[1] = u.y;
                mma_f16(o[nf], af, bf);
            }
        }
        __syncthreads();

        if (kt + 1 < NT) cp_V(kt + 1);
        if (kt + 2 < NT) cp_K(kt & 1, kt + 2);
    }

    // finalize: (b,t,dmodel-interleaved) fp16
#pragma unroll
    for (int hf = 0; hf < 2; hf++) {
        const float inv = (l_i[hf] > 0.f) ? (1.f / l_i[hf]) : 0.f;
        const int t = q0 + warp * 16 + lr + hf * 8;
#pragma unroll
        for (int nf = 0; nf < 8; nf++) {
            const int n = h * HDIM + nf * 8 + 2 * lc;
            const int offd = (n & ~15) + 2 * islot((n & 15) >> 1);
            __half2 hv = __floats2half2_rn(o[nf][hf * 2] * inv, o[nf][hf * 2 + 1] * inv);
            *(__half2*)&O[((size_t)(b * TQ + t)) * DMODEL + offd] = hv;
        }
    }
}

// ---------------- launch --------------------------------------------------------
extern "C" void kernel_launch(void* const* d_in, const int* in_sizes, int n_in,
                              void* d_out, int out_size)
{
    const float* x_q   = (const float*)d_in[0];
    const float* x_kv  = (const float*)d_in[1];
    const float* amask = (const float*)d_in[2];
    const unsigned char* kpm = (const unsigned char*)d_in[3];
    const float* Wq = (const float*)d_in[4];
    const float* Wk = (const float*)d_in[5];
    const float* Wv = (const float*)d_in[6];
    const float* Wo = (const float*)d_in[7];
    float* out = (float*)d_out;

    __half *qP, *kP, *vP, *oP, *xqP, *xkvP, *wqP, *wkP, *wvP, *woP, *mP;
    int* flagsP;
    cudaGetSymbolAddress((void**)&qP,  h_Q);
    cudaGetSymbolAddress((void**)&kP,  h_K);
    cudaGetSymbolAddress((void**)&vP,  h_V);
    cudaGetSymbolAddress((void**)&oP,  h_O);
    cudaGetSymbolAddress((void**)&xqP, h_Xq);
    cudaGetSymbolAddress((void**)&xkvP,h_Xkv);
    cudaGetSymbolAddress((void**)&wqP, h_Wq);
    cudaGetSymbolAddress((void**)&wkP, h_Wk);
    cudaGetSymbolAddress((void**)&wvP, h_Wv);
    cudaGetSymbolAddress((void**)&woP, h_Wo);
    cudaGetSymbolAddress((void**)&mP,  h_Mask);
    cudaGetSymbolAddress((void**)&flagsP, g_flags);

    const int XB = (MROWS * DMODEL) / 8 / 256;   // 4096
    const int WB = (DMODEL * DMODEL) / 8 / 256;  // 512
    cvt_all_kernel<<<2 * XB + 4 * WB, 256>>>(x_q, x_kv, Wq, Wk, Wv, Wo,
                                             xqP, xkvP, wqP, wkP, wvP, woP, flagsP);

    const int gemm_smem = 2 * (BM + BN) * GST * (int)sizeof(__half);   // 81920
    cudaFuncSetAttribute(gemm_qkv, cudaFuncAttributeMaxDynamicSharedMemorySize, gemm_smem);
    cudaFuncSetAttribute(gemm_out, cudaFuncAttributeMaxDynamicSharedMemorySize, gemm_smem);

    const float qscale = 0.125f * LOG2E;

    dim3 gqkv(DMODEL / BN, MROWS / BM, 4);   // (8, 64, 4)
    gemm_qkv<<<gqkv, 256, gemm_smem>>>(xqP, xkvP, wqP, wkP, wvP, qP, kP, vP, qscale,
                                       amask, mP, kpm, flagsP);

    const int attn_smem = (2 * KT * KSTR + HDIM * VSTR) * (int)sizeof(__half);  // 59392
    cudaFuncSetAttribute(attn_h16, cudaFuncAttributeMaxDynamicSharedMemorySize, attn_smem);
    dim3 ga(TQ / AQ, BATCH * NHEADS);     // (32, 64)
    attn_h16<<<ga, 128, attn_smem>>>(qP, kP, vP, mP, kpm, oP, flagsP);

    dim3 gout(DMODEL / BN, MROWS / BM);   // (8, 64)
    gemm_out<<<gout, 256, gemm_smem>>>(oP, woP, out);
}